// round 6
// baseline (speedup 1.0000x reference)
#include <cuda_runtime.h>
#include <cuda_bf16.h>
#include <cstdint>

#define G_EPS 1e-8f

#define BATCH 32768
#define NIN   256
#define NOUT  256
#define NG    5
#define KDIM  (NIN * NG)      // 1280

#define KT_W  64              // K columns per tile (64 bf16 = 128B SW128 row)
#define NT    (KDIM / KT_W)   // 20 K-tiles
#define BM    128             // M rows per CTA
#define NTHR  512             // 16 warps

// SMEM stage layout (bytes, within one stage)
#define OFF_AH 0
#define OFF_AL 16384
#define OFF_BH 32768
#define OFF_BL 65536
#define STAGE  98304
#define SM_DATA 1024
#define SMEM_TOTAL (SM_DATA + 2 * STAGE)   // 197632

__device__ float g_pmin[256];
__device__ float g_pmax[256];
__device__ float g_st[2];   // s, t for xn = s*x + t
__device__ __align__(16) __nv_bfloat16 g_Wh[NOUT * KDIM];
__device__ __align__(16) __nv_bfloat16 g_Wl[NOUT * KDIM];

// ---------------------------------------------------------------------------
// Helpers
// ---------------------------------------------------------------------------
__device__ __forceinline__ uint32_t smem_u32(const void* p) {
    uint32_t a;
    asm("{ .reg .u64 t; cvta.to.shared.u64 t, %1; cvt.u32.u64 %0, t; }"
        : "=r"(a) : "l"(p));
    return a;
}
__device__ __forceinline__ void cp_async16(uint32_t dst, const void* src) {
    asm volatile("cp.async.cg.shared.global [%0], [%1], 16;"
                 :: "r"(dst), "l"(src) : "memory");
}
#define CP_COMMIT() asm volatile("cp.async.commit_group;" ::: "memory")
#define CP_WAIT0()  asm volatile("cp.async.wait_group 0;" ::: "memory")

__device__ __forceinline__ void ldsm_x4(uint32_t* r, uint32_t addr) {
    asm volatile("ldmatrix.sync.aligned.m8n8.x4.shared.b16 {%0,%1,%2,%3}, [%4];"
                 : "=r"(r[0]), "=r"(r[1]), "=r"(r[2]), "=r"(r[3]) : "r"(addr));
}
__device__ __forceinline__ void ldsm_x2(uint32_t* r, uint32_t addr) {
    asm volatile("ldmatrix.sync.aligned.m8n8.x2.shared.b16 {%0,%1}, [%2];"
                 : "=r"(r[0]), "=r"(r[1]) : "r"(addr));
}
__device__ __forceinline__ void mma_16816(float* d, const uint32_t* a,
                                          const uint32_t* b) {
    asm volatile(
        "mma.sync.aligned.m16n8k16.row.col.f32.bf16.bf16.f32 "
        "{%0,%1,%2,%3}, {%4,%5,%6,%7}, {%8,%9}, {%0,%1,%2,%3};"
        : "+f"(d[0]), "+f"(d[1]), "+f"(d[2]), "+f"(d[3])
        : "r"(a[0]), "r"(a[1]), "r"(a[2]), "r"(a[3]), "r"(b[0]), "r"(b[1]));
}

// ---------------------------------------------------------------------------
// Kernel 1/2: global min/max reduction
// ---------------------------------------------------------------------------
__global__ void minmax_part_kernel(const float* __restrict__ x, int n4) {
    const float4* x4 = reinterpret_cast<const float4*>(x);
    float mn = 3.402823466e38f, mx = -3.402823466e38f;
    for (int i = blockIdx.x * blockDim.x + threadIdx.x; i < n4;
         i += gridDim.x * blockDim.x) {
        float4 v = x4[i];
        mn = fminf(mn, fminf(fminf(v.x, v.y), fminf(v.z, v.w)));
        mx = fmaxf(mx, fmaxf(fmaxf(v.x, v.y), fmaxf(v.z, v.w)));
    }
#pragma unroll
    for (int o = 16; o > 0; o >>= 1) {
        mn = fminf(mn, __shfl_xor_sync(0xffffffffu, mn, o));
        mx = fmaxf(mx, __shfl_xor_sync(0xffffffffu, mx, o));
    }
    __shared__ float smn[8], smx[8];
    int wid = threadIdx.x >> 5, lane = threadIdx.x & 31;
    if (lane == 0) { smn[wid] = mn; smx[wid] = mx; }
    __syncthreads();
    if (threadIdx.x < 8) {
        mn = smn[threadIdx.x];
        mx = smx[threadIdx.x];
#pragma unroll
        for (int o = 4; o > 0; o >>= 1) {
            mn = fminf(mn, __shfl_xor_sync(0xffu, mn, o));
            mx = fmaxf(mx, __shfl_xor_sync(0xffu, mx, o));
        }
        if (threadIdx.x == 0) { g_pmin[blockIdx.x] = mn; g_pmax[blockIdx.x] = mx; }
    }
}

__global__ void minmax_final_kernel() {
    int t = threadIdx.x;
    float mn = g_pmin[t], mx = g_pmax[t];
#pragma unroll
    for (int o = 16; o > 0; o >>= 1) {
        mn = fminf(mn, __shfl_xor_sync(0xffffffffu, mn, o));
        mx = fmaxf(mx, __shfl_xor_sync(0xffffffffu, mx, o));
    }
    __shared__ float smn[8], smx[8];
    int wid = t >> 5, lane = t & 31;
    if (lane == 0) { smn[wid] = mn; smx[wid] = mx; }
    __syncthreads();
    if (t < 8) {
        mn = smn[t];
        mx = smx[t];
#pragma unroll
        for (int o = 4; o > 0; o >>= 1) {
            mn = fminf(mn, __shfl_xor_sync(0xffu, mn, o));
            mx = fmaxf(mx, __shfl_xor_sync(0xffu, mx, o));
        }
        if (t == 0) {
            float range = mx - mn + G_EPS;
            g_st[0] = 2.0f / range;
            g_st[1] = -2.0f * mn / range - 1.0f;
        }
    }
}

// ---------------------------------------------------------------------------
// Kernel 3: W = coef*scale, split into bf16 hi/lo
// ---------------------------------------------------------------------------
__global__ void wprep_kernel(const float* __restrict__ coef,
                             const float* __restrict__ scale) {
    int idx = blockIdx.x * blockDim.x + threadIdx.x;
    if (idx < NOUT * KDIM) {
        int o   = idx / KDIM;
        int rem = idx - o * KDIM;
        int i   = rem / NG;
        float w = coef[idx] * scale[o * NIN + i];
        __nv_bfloat16 wh = __float2bfloat16_rn(w);
        float res = w - __bfloat162float(wh);
        g_Wh[idx] = wh;
        g_Wl[idx] = __float2bfloat16_rn(res);
    }
}

// ---------------------------------------------------------------------------
// A-tile generation: 16 consecutive K columns of one row, phase P0 = ks%5
// ---------------------------------------------------------------------------
template <int P0>
__device__ __forceinline__ void gen_span16(const float* __restrict__ xr, int i0,
                                           float s, float tt,
                                           float g0, float g1, float g2,
                                           float g3, float g4,
                                           char* tAh, char* tAl, int rowbyte) {
    float v0 = 0.f, v1 = 0.f, v2 = 0.f, v3 = 0.f, v4 = 0.f;
    int i = i0;
#pragma unroll
    for (int q = 0; q < 2; q++) {
        uint32_t hp[4], lp[4];
#pragma unroll
        for (int u = 0; u < 4; u++) {
            unsigned short hh[2], ll[2];
#pragma unroll
            for (int e = 0; e < 2; e++) {
                const int j = q * 8 + u * 2 + e;
                const int g = (P0 + j) % 5;
                if (g == 0 || j == 0) {
                    if (g == 0 && j > 0) i++;
                    float xv = __ldg(xr + i);
                    float xn = fmaf(xv, s, tt);
                    float d;
                    d = fabsf(xn - g0); v0 = fmaxf(fmaf(-d * d, d, 1.0f), 0.0f);
                    d = fabsf(xn - g1); v1 = fmaxf(fmaf(-d * d, d, 1.0f), 0.0f);
                    d = fabsf(xn - g2); v2 = fmaxf(fmaf(-d * d, d, 1.0f), 0.0f);
                    d = fabsf(xn - g3); v3 = fmaxf(fmaf(-d * d, d, 1.0f), 0.0f);
                    d = fabsf(xn - g4); v4 = fmaxf(fmaf(-d * d, d, 1.0f), 0.0f);
                    float inv = __fdividef(1.0f, v0 + v1 + v2 + v3 + v4 + G_EPS);
                    v0 *= inv; v1 *= inv; v2 *= inv; v3 *= inv; v4 *= inv;
                }
                float v = (g == 0) ? v0 : (g == 1) ? v1 : (g == 2) ? v2
                                        : (g == 3) ? v3 : v4;
                __nv_bfloat16 bh = __float2bfloat16_rn(v);
                float rem = v - __bfloat162float(bh);
                __nv_bfloat16 bl = __float2bfloat16_rn(rem);
                hh[e] = __bfloat16_as_ushort(bh);
                ll[e] = __bfloat16_as_ushort(bl);
            }
            hp[u] = (uint32_t)hh[0] | ((uint32_t)hh[1] << 16);
            lp[u] = (uint32_t)ll[0] | ((uint32_t)ll[1] << 16);
        }
        int off = rowbyte + q * 16;
        int sw  = off ^ ((off >> 3) & 0x70);
        *reinterpret_cast<uint4*>(tAh + sw) = make_uint4(hp[0], hp[1], hp[2], hp[3]);
        *reinterpret_cast<uint4*>(tAl + sw) = make_uint4(lp[0], lp[1], lp[2], lp[3]);
    }
}

// Producers: fill one stage (Ah/Al/Bh/Bl, SW128 swizzled), 512 threads
__device__ __forceinline__ void produce_B(uint32_t stage_u32, int kt, int t) {
    const char* wh = reinterpret_cast<const char*>(g_Wh) + kt * 128;
    const char* wl = reinterpret_cast<const char*>(g_Wl) + kt * 128;
#pragma unroll
    for (int z = 0; z < 4; z++) {
        int c   = t + z * NTHR;
        int n   = c >> 3;
        int k16 = c & 7;
        size_t gb = (size_t)n * (KDIM * 2) + k16 * 16;
        int off = n * 128 + k16 * 16;
        int sw  = off ^ ((off >> 3) & 0x70);
        cp_async16(stage_u32 + OFF_BH + sw, wh + gb);
        cp_async16(stage_u32 + OFF_BL + sw, wl + gb);
    }
    CP_COMMIT();
}

__device__ __forceinline__ void produce_A(char* stage, int kt, int quarter,
                                          int rowbyte,
                                          const float* __restrict__ xr,
                                          float s, float tt,
                                          float g0, float g1, float g2,
                                          float g3, float g4) {
    int ks = kt * KT_W + quarter * 16;
    int i0 = ks / 5;
    switch (ks % 5) {
    case 0: gen_span16<0>(xr, i0, s, tt, g0, g1, g2, g3, g4,
                          stage + OFF_AH, stage + OFF_AL, rowbyte); break;
    case 1: gen_span16<1>(xr, i0, s, tt, g0, g1, g2, g3, g4,
                          stage + OFF_AH, stage + OFF_AL, rowbyte); break;
    case 2: gen_span16<2>(xr, i0, s, tt, g0, g1, g2, g3, g4,
                          stage + OFF_AH, stage + OFF_AL, rowbyte); break;
    case 3: gen_span16<3>(xr, i0, s, tt, g0, g1, g2, g3, g4,
                          stage + OFF_AH, stage + OFF_AL, rowbyte); break;
    default: gen_span16<4>(xr, i0, s, tt, g0, g1, g2, g3, g4,
                           stage + OFF_AH, stage + OFF_AL, rowbyte); break;
    }
}

// ---------------------------------------------------------------------------
// Main kernel: per-CTA 128x256 GEMM over K=1280 (20 tiles of 64),
// 3 bf16 split passes (ah*wh + al*wh + ah*wl), mma.sync.m16n8k16.
// 16 warps: warp w -> rows [mw*16, mw*16+16), cols [nh*128, nh*128+128).
// Double-buffered stages: produce(kt+1) overlaps consume(kt).
// ---------------------------------------------------------------------------
__global__ void __launch_bounds__(NTHR, 1)
kan_mma_kernel(const float* __restrict__ x, const float* __restrict__ grid,
               const float* __restrict__ bias, float* __restrict__ out) {
    extern __shared__ char dsm[];
    const uint32_t sb = smem_u32(dsm);
    const int t = threadIdx.x;
    const int rowBase = blockIdx.x * BM;

    const float s  = g_st[0];
    const float tt = g_st[1];
    const float gr0 = __ldg(grid + 0), gr1 = __ldg(grid + 1),
                gr2 = __ldg(grid + 2), gr3 = __ldg(grid + 3),
                gr4 = __ldg(grid + 4);

    // Producer mapping: thread -> (row, 16-col quarter)
    const int r       = t & 127;
    const int quarter = t >> 7;           // 0..3
    const int rowbyte = r * 128 + quarter * 32;
    const float* xr   = x + (size_t)(rowBase + r) * NIN;

    // Consumer mapping
    const int w    = t >> 5, lane = t & 31;
    const int mw   = w & 7;               // M group (16 rows)
    const int nh   = w >> 3;              // N half (128 cols)
    const int a_row = mw * 16 + (lane & 15);
    const int a_kb0 = (lane >> 4) * 16;
    const int b_n7  = lane & 7;
    const int b_kb0 = ((lane >> 3) & 1) * 16;

    float acc[16][4];
#pragma unroll
    for (int nb = 0; nb < 16; nb++)
#pragma unroll
        for (int j = 0; j < 4; j++) acc[nb][j] = 0.0f;

    // Prologue: produce tile 0 into stage 0
    produce_B(sb + SM_DATA, 0, t);
    produce_A(dsm + SM_DATA, 0, quarter, rowbyte, xr, s, tt,
              gr0, gr1, gr2, gr3, gr4);
    CP_WAIT0();
    __syncthreads();

    for (int kt = 0; kt < NT; kt++) {
        const int b = kt & 1;
        const uint32_t cbase = sb + SM_DATA + b * STAGE;

        // ---- produce next tile into the other stage (overlaps MMA) ----
        if (kt + 1 < NT) {
            uint32_t pbase = sb + SM_DATA + (1 - b) * STAGE;
            produce_B(pbase, kt + 1, t);
            produce_A(dsm + SM_DATA + (1 - b) * STAGE, kt + 1, quarter, rowbyte,
                      xr, s, tt, gr0, gr1, gr2, gr3, gr4);
        }

        // ---- consume current tile ----
#pragma unroll
        for (int ks = 0; ks < 4; ks++) {
            int aoff = a_row * 128 + ks * 32 + a_kb0;
            int asw  = aoff ^ ((aoff >> 3) & 0x70);
            uint32_t ah[4], al[4];
            ldsm_x4(ah, cbase + OFF_AH + asw);
            ldsm_x4(al, cbase + OFF_AL + asw);

            int boff = b_n7 * 128 + ks * 32 + b_kb0;
            int bsw  = boff ^ ((boff >> 3) & 0x70);
            uint32_t bhA = cbase + OFF_BH + bsw + nh * 16384;
            uint32_t blA = cbase + OFF_BL + bsw + nh * 16384;

            uint32_t bh[2], bl[2], bh2[2], bl2[2];
            ldsm_x2(bh, bhA);
            ldsm_x2(bl, blA);
#pragma unroll
            for (int nb = 0; nb < 16; nb++) {
                if (nb + 1 < 16) {
                    ldsm_x2(bh2, bhA + (nb + 1) * 1024);
                    ldsm_x2(bl2, blA + (nb + 1) * 1024);
                }
                mma_16816(acc[nb], ah, bh);
                mma_16816(acc[nb], al, bh);
                mma_16816(acc[nb], ah, bl);
                bh[0] = bh2[0]; bh[1] = bh2[1];
                bl[0] = bl2[0]; bl[1] = bl2[1];
            }
        }

        if (kt + 1 < NT) CP_WAIT0();
        __syncthreads();
    }

    // ---- epilogue ----
    {
        const int er = lane >> 2;
        const int ec = (lane & 3) * 2;
        const size_t row0 = (size_t)(rowBase + mw * 16 + er);
#pragma unroll
        for (int nb = 0; nb < 16; nb++) {
            int c = nh * 128 + nb * 8 + ec;
            float2 b2 = *reinterpret_cast<const float2*>(bias + c);
            float2 v0, v1;
            v0.x = acc[nb][0] + b2.x;
            v0.y = acc[nb][1] + b2.y;
            v1.x = acc[nb][2] + b2.x;
            v1.y = acc[nb][3] + b2.y;
            *reinterpret_cast<float2*>(out + row0 * NOUT + c) = v0;
            *reinterpret_cast<float2*>(out + (row0 + 8) * NOUT + c) = v1;
        }
    }
}

// ---------------------------------------------------------------------------
extern "C" void kernel_launch(void* const* d_in, const int* in_sizes, int n_in,
                              void* d_out, int out_size) {
    const float* x     = (const float*)d_in[0];
    const float* grid  = (const float*)d_in[1];
    const float* coef  = (const float*)d_in[2];
    const float* scale = (const float*)d_in[3];
    const float* bias  = (const float*)d_in[4];
    float* out = (float*)d_out;

    int n = in_sizes[0];
    minmax_part_kernel<<<256, 256>>>(x, n / 4);
    minmax_final_kernel<<<1, 256>>>();
    wprep_kernel<<<(NOUT * KDIM + 255) / 256, 256>>>(coef, scale);

    cudaFuncSetAttribute(kan_mma_kernel,
                         cudaFuncAttributeMaxDynamicSharedMemorySize,
                         SMEM_TOTAL);
    kan_mma_kernel<<<BATCH / BM, NTHR, SMEM_TOTAL>>>(x, grid, bias, out);
}

// round 7
// speedup vs baseline: 1.0197x; 1.0197x over previous
#include <cuda_runtime.h>
#include <cuda_fp16.h>
#include <cstdint>

#define G_EPS 1e-8f

#define BATCH 32768
#define NIN   256
#define NOUT  256
#define NG    5
#define KDIM  (NIN * NG)      // 1280

#define KT_W  64              // K columns per tile (64 fp16 = 128B SW128 row)
#define NT    (KDIM / KT_W)   // 20 K-tiles
#define BM    128             // M rows per CTA
#define BN    128             // N cols per CTA
#define NTHR  256             // 8 warps

// SMEM layout (single stage): A 16KB, Bh 16KB, Bl 16KB
#define OFF_A  0
#define OFF_BH 16384
#define OFF_BL 32768
#define SM_DATA 1024
#define SMEM_TOTAL (SM_DATA + 49152)   // 50176 -> 2 CTAs/SM fits

__device__ float g_pmin[256];
__device__ float g_pmax[256];
__device__ float g_st[2];   // s, t for xn = s*x + t
__device__ __align__(16) __half g_Wh[NOUT * KDIM];
__device__ __align__(16) __half g_Wl[NOUT * KDIM];

// ---------------------------------------------------------------------------
// Helpers
// ---------------------------------------------------------------------------
__device__ __forceinline__ uint32_t smem_u32(const void* p) {
    uint32_t a;
    asm("{ .reg .u64 t; cvta.to.shared.u64 t, %1; cvt.u32.u64 %0, t; }"
        : "=r"(a) : "l"(p));
    return a;
}
__device__ __forceinline__ void ldsm_x4(uint32_t* r, uint32_t addr) {
    asm volatile("ldmatrix.sync.aligned.m8n8.x4.shared.b16 {%0,%1,%2,%3}, [%4];"
                 : "=r"(r[0]), "=r"(r[1]), "=r"(r[2]), "=r"(r[3]) : "r"(addr));
}
__device__ __forceinline__ void ldsm_x2(uint32_t* r, uint32_t addr) {
    asm volatile("ldmatrix.sync.aligned.m8n8.x2.shared.b16 {%0,%1}, [%2];"
                 : "=r"(r[0]), "=r"(r[1]) : "r"(addr));
}
__device__ __forceinline__ void mma_16816(float* d, const uint32_t* a,
                                          const uint32_t* b) {
    asm volatile(
        "mma.sync.aligned.m16n8k16.row.col.f32.f16.f16.f32 "
        "{%0,%1,%2,%3}, {%4,%5,%6,%7}, {%8,%9}, {%0,%1,%2,%3};"
        : "+f"(d[0]), "+f"(d[1]), "+f"(d[2]), "+f"(d[3])
        : "r"(a[0]), "r"(a[1]), "r"(a[2]), "r"(a[3]), "r"(b[0]), "r"(b[1]));
}

// ---------------------------------------------------------------------------
// Kernel 1/2: global min/max reduction
// ---------------------------------------------------------------------------
__global__ void minmax_part_kernel(const float* __restrict__ x, int n4) {
    const float4* x4 = reinterpret_cast<const float4*>(x);
    float mn = 3.402823466e38f, mx = -3.402823466e38f;
    for (int i = blockIdx.x * blockDim.x + threadIdx.x; i < n4;
         i += gridDim.x * blockDim.x) {
        float4 v = x4[i];
        mn = fminf(mn, fminf(fminf(v.x, v.y), fminf(v.z, v.w)));
        mx = fmaxf(mx, fmaxf(fmaxf(v.x, v.y), fmaxf(v.z, v.w)));
    }
#pragma unroll
    for (int o = 16; o > 0; o >>= 1) {
        mn = fminf(mn, __shfl_xor_sync(0xffffffffu, mn, o));
        mx = fmaxf(mx, __shfl_xor_sync(0xffffffffu, mx, o));
    }
    __shared__ float smn[8], smx[8];
    int wid = threadIdx.x >> 5, lane = threadIdx.x & 31;
    if (lane == 0) { smn[wid] = mn; smx[wid] = mx; }
    __syncthreads();
    if (threadIdx.x < 8) {
        mn = smn[threadIdx.x];
        mx = smx[threadIdx.x];
#pragma unroll
        for (int o = 4; o > 0; o >>= 1) {
            mn = fminf(mn, __shfl_xor_sync(0xffu, mn, o));
            mx = fmaxf(mx, __shfl_xor_sync(0xffu, mx, o));
        }
        if (threadIdx.x == 0) { g_pmin[blockIdx.x] = mn; g_pmax[blockIdx.x] = mx; }
    }
}

__global__ void minmax_final_kernel() {
    int t = threadIdx.x;
    float mn = g_pmin[t], mx = g_pmax[t];
#pragma unroll
    for (int o = 16; o > 0; o >>= 1) {
        mn = fminf(mn, __shfl_xor_sync(0xffffffffu, mn, o));
        mx = fmaxf(mx, __shfl_xor_sync(0xffffffffu, mx, o));
    }
    __shared__ float smn[8], smx[8];
    int wid = t >> 5, lane = t & 31;
    if (lane == 0) { smn[wid] = mn; smx[wid] = mx; }
    __syncthreads();
    if (t < 8) {
        mn = smn[t];
        mx = smx[t];
#pragma unroll
        for (int o = 4; o > 0; o >>= 1) {
            mn = fminf(mn, __shfl_xor_sync(0xffu, mn, o));
            mx = fmaxf(mx, __shfl_xor_sync(0xffu, mx, o));
        }
        if (t == 0) {
            float range = mx - mn + G_EPS;
            g_st[0] = 2.0f / range;
            g_st[1] = -2.0f * mn / range - 1.0f;
        }
    }
}

// ---------------------------------------------------------------------------
// Kernel 3: W = coef*scale, split into fp16 hi/lo (captures w to ~2^-22)
// ---------------------------------------------------------------------------
__global__ void wprep_kernel(const float* __restrict__ coef,
                             const float* __restrict__ scale) {
    int idx = blockIdx.x * blockDim.x + threadIdx.x;
    if (idx < NOUT * KDIM) {
        int o   = idx / KDIM;
        int rem = idx - o * KDIM;
        int i   = rem / NG;
        float w = coef[idx] * scale[o * NIN + i];
        __half wh = __float2half_rn(w);
        float res = w - __half2float(wh);
        g_Wh[idx] = wh;
        g_Wl[idx] = __float2half_rn(res);
    }
}

// ---------------------------------------------------------------------------
// A-tile generation: 32 consecutive K columns of one row, fp16 only.
// Phase P0 = kstart % 5 is compile-time.
// ---------------------------------------------------------------------------
template <int P0>
__device__ __forceinline__ void gen_span(const float* __restrict__ xr, int i0,
                                         float s, float tt,
                                         float g0, float g1, float g2,
                                         float g3, float g4,
                                         char* tA, int rowbyte) {
    float v0 = 0.f, v1 = 0.f, v2 = 0.f, v3 = 0.f, v4 = 0.f;
    int i = i0;
#pragma unroll
    for (int q = 0; q < 4; q++) {
        uint32_t hp[4];
#pragma unroll
        for (int u = 0; u < 4; u++) {
            unsigned short hh[2];
#pragma unroll
            for (int e = 0; e < 2; e++) {
                const int j = q * 8 + u * 2 + e;
                const int g = (P0 + j) % 5;
                if (g == 0 || j == 0) {
                    if (g == 0 && j > 0) i++;
                    float xv = __ldg(xr + i);
                    float xn = fmaf(xv, s, tt);
                    float d;
                    d = fabsf(xn - g0); v0 = fmaxf(fmaf(-d * d, d, 1.0f), 0.0f);
                    d = fabsf(xn - g1); v1 = fmaxf(fmaf(-d * d, d, 1.0f), 0.0f);
                    d = fabsf(xn - g2); v2 = fmaxf(fmaf(-d * d, d, 1.0f), 0.0f);
                    d = fabsf(xn - g3); v3 = fmaxf(fmaf(-d * d, d, 1.0f), 0.0f);
                    d = fabsf(xn - g4); v4 = fmaxf(fmaf(-d * d, d, 1.0f), 0.0f);
                    float inv = __fdividef(1.0f, v0 + v1 + v2 + v3 + v4 + G_EPS);
                    v0 *= inv; v1 *= inv; v2 *= inv; v3 *= inv; v4 *= inv;
                }
                float v = (g == 0) ? v0 : (g == 1) ? v1 : (g == 2) ? v2
                                        : (g == 3) ? v3 : v4;
                hh[e] = __half_as_ushort(__float2half_rn(v));
            }
            hp[u] = (uint32_t)hh[0] | ((uint32_t)hh[1] << 16);
        }
        int off = rowbyte + q * 16;
        int sw  = off ^ ((off >> 3) & 0x70);
        *reinterpret_cast<uint4*>(tA + sw) = make_uint4(hp[0], hp[1], hp[2], hp[3]);
    }
}

// Producers (256 threads)
__device__ __forceinline__ void produce_B(char* stage, int kt, int n0, int t) {
    const char* wh = reinterpret_cast<const char*>(g_Wh) +
                     (size_t)n0 * (KDIM * 2) + kt * 128;
    const char* wl = reinterpret_cast<const char*>(g_Wl) +
                     (size_t)n0 * (KDIM * 2) + kt * 128;
#pragma unroll
    for (int z = 0; z < 4; z++) {
        int c   = t + z * NTHR;           // 0..1023
        int n   = c >> 3;                 // 0..127
        int k16 = c & 7;
        size_t gb = (size_t)n * (KDIM * 2) + k16 * 16;
        uint4 vh = *reinterpret_cast<const uint4*>(wh + gb);
        uint4 vl = *reinterpret_cast<const uint4*>(wl + gb);
        int off = n * 128 + k16 * 16;
        int sw  = off ^ ((off >> 3) & 0x70);
        *reinterpret_cast<uint4*>(stage + OFF_BH + sw) = vh;
        *reinterpret_cast<uint4*>(stage + OFF_BL + sw) = vl;
    }
}

__device__ __forceinline__ void produce_A(char* stage, int kt, int half,
                                          int rowbyte,
                                          const float* __restrict__ xr,
                                          float s, float tt,
                                          float g0, float g1, float g2,
                                          float g3, float g4) {
    int ks = kt * KT_W + half * 32;
    int i0 = ks / 5;
    switch (ks % 5) {
    case 0: gen_span<0>(xr, i0, s, tt, g0, g1, g2, g3, g4,
                        stage + OFF_A, rowbyte); break;
    case 1: gen_span<1>(xr, i0, s, tt, g0, g1, g2, g3, g4,
                        stage + OFF_A, rowbyte); break;
    case 2: gen_span<2>(xr, i0, s, tt, g0, g1, g2, g3, g4,
                        stage + OFF_A, rowbyte); break;
    case 3: gen_span<3>(xr, i0, s, tt, g0, g1, g2, g3, g4,
                        stage + OFF_A, rowbyte); break;
    default: gen_span<4>(xr, i0, s, tt, g0, g1, g2, g3, g4,
                         stage + OFF_A, rowbyte); break;
    }
}

// ---------------------------------------------------------------------------
// Main kernel: per-CTA 128x128 GEMM over K=1280 (20 tiles of 64),
// 2 fp16 passes (a*wh + a*wl), mma.sync.m16n8k16.f16, occupancy 2.
// 8 warps: warp w -> rows [w*16, w*16+16), all 128 cols.
// ---------------------------------------------------------------------------
__global__ void __launch_bounds__(NTHR, 2)
kan_mma_kernel(const float* __restrict__ x, const float* __restrict__ grid,
               const float* __restrict__ bias, float* __restrict__ out) {
    extern __shared__ char dsm[];
    const uint32_t sb = smem_u32(dsm);
    const int t = threadIdx.x;
    const int rowBase = blockIdx.x * BM;
    const int n0      = blockIdx.y * BN;

    const float s  = g_st[0];
    const float tt = g_st[1];
    const float gr0 = __ldg(grid + 0), gr1 = __ldg(grid + 1),
                gr2 = __ldg(grid + 2), gr3 = __ldg(grid + 3),
                gr4 = __ldg(grid + 4);

    // Producer mapping: thread -> (row, 32-col half)
    const int r       = t & 127;
    const int half    = t >> 7;           // 0..1
    const int rowbyte = r * 128 + half * 64;
    const float* xr   = x + (size_t)(rowBase + r) * NIN;

    // Consumer mapping: warp w owns rows [w*16, w*16+16), all 128 cols
    const int w = t >> 5, lane = t & 31;
    const int a_row = w * 16 + (lane & 15);
    const int a_kb0 = (lane >> 4) * 16;
    const int b_n7  = lane & 7;
    const int b_kb0 = ((lane >> 3) & 1) * 16;

    float acc[16][4];
#pragma unroll
    for (int nb = 0; nb < 16; nb++)
#pragma unroll
        for (int j = 0; j < 4; j++) acc[nb][j] = 0.0f;

    char* stage = dsm + SM_DATA;
    const uint32_t cbase = sb + SM_DATA;

    for (int kt = 0; kt < NT; kt++) {
        produce_B(stage, kt, n0, t);
        produce_A(stage, kt, half, rowbyte, xr, s, tt, gr0, gr1, gr2, gr3, gr4);
        __syncthreads();

#pragma unroll
        for (int ks = 0; ks < 4; ks++) {
            int aoff = a_row * 128 + ks * 32 + a_kb0;
            int asw  = aoff ^ ((aoff >> 3) & 0x70);
            uint32_t af[4];
            ldsm_x4(af, cbase + OFF_A + asw);

            int boff = b_n7 * 128 + ks * 32 + b_kb0;
            int bsw  = boff ^ ((boff >> 3) & 0x70);
            uint32_t bhA = cbase + OFF_BH + bsw;
            uint32_t blA = cbase + OFF_BL + bsw;

            uint32_t bh[2], bl[2], bh2[2], bl2[2];
            ldsm_x2(bh, bhA);
            ldsm_x2(bl, blA);
#pragma unroll
            for (int nb = 0; nb < 16; nb++) {
                if (nb + 1 < 16) {
                    ldsm_x2(bh2, bhA + (nb + 1) * 1024);
                    ldsm_x2(bl2, blA + (nb + 1) * 1024);
                }
                mma_16816(acc[nb], af, bh);
                mma_16816(acc[nb], af, bl);
                bh[0] = bh2[0]; bh[1] = bh2[1];
                bl[0] = bl2[0]; bl[1] = bl2[1];
            }
        }
        __syncthreads();
    }

    // ---- epilogue ----
    {
        const int er = lane >> 2;
        const int ec = (lane & 3) * 2;
        const size_t row0 = (size_t)(rowBase + w * 16 + er);
#pragma unroll
        for (int nb = 0; nb < 16; nb++) {
            int c = n0 + nb * 8 + ec;
            float2 b2 = *reinterpret_cast<const float2*>(bias + c);
            float2 v0, v1;
            v0.x = acc[nb][0] + b2.x;
            v0.y = acc[nb][1] + b2.y;
            v1.x = acc[nb][2] + b2.x;
            v1.y = acc[nb][3] + b2.y;
            *reinterpret_cast<float2*>(out + row0 * NOUT + c) = v0;
            *reinterpret_cast<float2*>(out + (row0 + 8) * NOUT + c) = v1;
        }
    }
}

// ---------------------------------------------------------------------------
extern "C" void kernel_launch(void* const* d_in, const int* in_sizes, int n_in,
                              void* d_out, int out_size) {
    const float* x     = (const float*)d_in[0];
    const float* grid  = (const float*)d_in[1];
    const float* coef  = (const float*)d_in[2];
    const float* scale = (const float*)d_in[3];
    const float* bias  = (const float*)d_in[4];
    float* out = (float*)d_out;

    int n = in_sizes[0];
    minmax_part_kernel<<<256, 256>>>(x, n / 4);
    minmax_final_kernel<<<1, 256>>>();
    wprep_kernel<<<(NOUT * KDIM + 255) / 256, 256>>>(coef, scale);

    cudaFuncSetAttribute(kan_mma_kernel,
                         cudaFuncAttributeMaxDynamicSharedMemorySize,
                         SMEM_TOTAL);
    dim3 g(BATCH / BM, NOUT / BN);
    kan_mma_kernel<<<g, NTHR, SMEM_TOTAL>>>(x, grid, bias, out);
}

// round 10
// speedup vs baseline: 1.2287x; 1.2049x over previous
#include <cuda_runtime.h>
#include <cuda_fp16.h>
#include <cstdint>

#define G_EPS 1e-8f

#define BATCH 32768
#define NIN   256
#define NOUT  256
#define NG    5
#define KDIM  (NIN * NG)      // 1280

#define KT_W  64              // K columns per tile (64 fp16 = 128B SW128 row)
#define NT    (KDIM / KT_W)   // 20 K-tiles
#define BM    128             // M rows per CTA
#define BN    128             // N cols per CTA
#define NTHR  256             // 8 warps

// SMEM layout (single stage): A 16KB, Bh 16KB, Bl 16KB
#define OFF_A  0
#define OFF_BH 16384
#define OFF_BL 32768
#define SM_DATA 1024
#define SMEM_TOTAL (SM_DATA + 49152)   // 50176 -> 2 CTAs/SM

__device__ float g_pmin[256];
__device__ float g_pmax[256];
__device__ float g_st[2];   // s, t for xn = s*x + t
__device__ __align__(16) __half g_Wh[NOUT * KDIM];
__device__ __align__(16) __half g_Wl[NOUT * KDIM];

// ---------------------------------------------------------------------------
// Helpers
// ---------------------------------------------------------------------------
__device__ __forceinline__ uint32_t smem_u32(const void* p) {
    uint32_t a;
    asm("{ .reg .u64 t; cvta.to.shared.u64 t, %1; cvt.u32.u64 %0, t; }"
        : "=r"(a) : "l"(p));
    return a;
}
__device__ __forceinline__ void cp_async16(uint32_t dst, const void* src) {
    asm volatile("cp.async.cg.shared.global [%0], [%1], 16;"
                 :: "r"(dst), "l"(src) : "memory");
}
#define CP_COMMIT() asm volatile("cp.async.commit_group;" ::: "memory")
#define CP_WAIT0()  asm volatile("cp.async.wait_group 0;" ::: "memory")

__device__ __forceinline__ void ldsm_x4(uint32_t* r, uint32_t addr) {
    asm volatile("ldmatrix.sync.aligned.m8n8.x4.shared.b16 {%0,%1,%2,%3}, [%4];"
                 : "=r"(r[0]), "=r"(r[1]), "=r"(r[2]), "=r"(r[3]) : "r"(addr));
}
__device__ __forceinline__ void ldsm_x2(uint32_t* r, uint32_t addr) {
    asm volatile("ldmatrix.sync.aligned.m8n8.x2.shared.b16 {%0,%1}, [%2];"
                 : "=r"(r[0]), "=r"(r[1]) : "r"(addr));
}
__device__ __forceinline__ void mma_16816(float* d, const uint32_t* a,
                                          const uint32_t* b) {
    asm volatile(
        "mma.sync.aligned.m16n8k16.row.col.f32.f16.f16.f32 "
        "{%0,%1,%2,%3}, {%4,%5,%6,%7}, {%8,%9}, {%0,%1,%2,%3};"
        : "+f"(d[0]), "+f"(d[1]), "+f"(d[2]), "+f"(d[3])
        : "r"(a[0]), "r"(a[1]), "r"(a[2]), "r"(a[3]), "r"(b[0]), "r"(b[1]));
}

// ---------------------------------------------------------------------------
// Kernel 1/2: global min/max reduction
// ---------------------------------------------------------------------------
__global__ void minmax_part_kernel(const float* __restrict__ x, int n4) {
    const float4* x4 = reinterpret_cast<const float4*>(x);
    float mn = 3.402823466e38f, mx = -3.402823466e38f;
    for (int i = blockIdx.x * blockDim.x + threadIdx.x; i < n4;
         i += gridDim.x * blockDim.x) {
        float4 v = x4[i];
        mn = fminf(mn, fminf(fminf(v.x, v.y), fminf(v.z, v.w)));
        mx = fmaxf(mx, fmaxf(fmaxf(v.x, v.y), fmaxf(v.z, v.w)));
    }
#pragma unroll
    for (int o = 16; o > 0; o >>= 1) {
        mn = fminf(mn, __shfl_xor_sync(0xffffffffu, mn, o));
        mx = fmaxf(mx, __shfl_xor_sync(0xffffffffu, mx, o));
    }
    __shared__ float smn[8], smx[8];
    int wid = threadIdx.x >> 5, lane = threadIdx.x & 31;
    if (lane == 0) { smn[wid] = mn; smx[wid] = mx; }
    __syncthreads();
    if (threadIdx.x < 8) {
        mn = smn[threadIdx.x];
        mx = smx[threadIdx.x];
#pragma unroll
        for (int o = 4; o > 0; o >>= 1) {
            mn = fminf(mn, __shfl_xor_sync(0xffu, mn, o));
            mx = fmaxf(mx, __shfl_xor_sync(0xffu, mx, o));
        }
        if (threadIdx.x == 0) { g_pmin[blockIdx.x] = mn; g_pmax[blockIdx.x] = mx; }
    }
}

__global__ void minmax_final_kernel() {
    int t = threadIdx.x;
    float mn = g_pmin[t], mx = g_pmax[t];
#pragma unroll
    for (int o = 16; o > 0; o >>= 1) {
        mn = fminf(mn, __shfl_xor_sync(0xffffffffu, mn, o));
        mx = fmaxf(mx, __shfl_xor_sync(0xffffffffu, mx, o));
    }
    __shared__ float smn[8], smx[8];
    int wid = t >> 5, lane = t & 31;
    if (lane == 0) { smn[wid] = mn; smx[wid] = mx; }
    __syncthreads();
    if (t < 8) {
        mn = smn[t];
        mx = smx[t];
#pragma unroll
        for (int o = 4; o > 0; o >>= 1) {
            mn = fminf(mn, __shfl_xor_sync(0xffu, mn, o));
            mx = fmaxf(mx, __shfl_xor_sync(0xffu, mx, o));
        }
        if (t == 0) {
            float range = mx - mn + G_EPS;
            g_st[0] = 2.0f / range;
            g_st[1] = -2.0f * mn / range - 1.0f;
        }
    }
}

// ---------------------------------------------------------------------------
// Kernel 3: W = coef*scale, split into fp16 hi/lo
// ---------------------------------------------------------------------------
__global__ void wprep_kernel(const float* __restrict__ coef,
                             const float* __restrict__ scale) {
    int idx = blockIdx.x * blockDim.x + threadIdx.x;
    if (idx < NOUT * KDIM) {
        int o   = idx / KDIM;
        int rem = idx - o * KDIM;
        int i   = rem / NG;
        float w = coef[idx] * scale[o * NIN + i];
        __half wh = __float2half_rn(w);
        float res = w - __half2float(wh);
        g_Wh[idx] = wh;
        g_Wl[idx] = __float2half_rn(res);
    }
}

// ---------------------------------------------------------------------------
// A-tile generation: 32 consecutive K columns of one row, fp16.
// Phase P0 = kstart % 5 is compile-time.
// ---------------------------------------------------------------------------
template <int P0>
__device__ __forceinline__ void gen_span(const float* __restrict__ xr, int i0,
                                         float s, float tt,
                                         float g0, float g1, float g2,
                                         float g3, float g4,
                                         char* tA, int rowbyte) {
    float v0 = 0.f, v1 = 0.f, v2 = 0.f, v3 = 0.f, v4 = 0.f;
    int i = i0;
#pragma unroll
    for (int q = 0; q < 4; q++) {
        uint32_t hp[4];
#pragma unroll
        for (int u = 0; u < 4; u++) {
            unsigned short hh[2];
#pragma unroll
            for (int e = 0; e < 2; e++) {
                const int j = q * 8 + u * 2 + e;
                const int g = (P0 + j) % 5;
                if (g == 0 || j == 0) {
                    if (g == 0 && j > 0) i++;
                    float xv = __ldg(xr + i);
                    float xn = fmaf(xv, s, tt);
                    float d;
                    d = fabsf(xn - g0); v0 = fmaxf(fmaf(-d * d, d, 1.0f), 0.0f);
                    d = fabsf(xn - g1); v1 = fmaxf(fmaf(-d * d, d, 1.0f), 0.0f);
                    d = fabsf(xn - g2); v2 = fmaxf(fmaf(-d * d, d, 1.0f), 0.0f);
                    d = fabsf(xn - g3); v3 = fmaxf(fmaf(-d * d, d, 1.0f), 0.0f);
                    d = fabsf(xn - g4); v4 = fmaxf(fmaf(-d * d, d, 1.0f), 0.0f);
                    float inv = __fdividef(1.0f, v0 + v1 + v2 + v3 + v4 + G_EPS);
                    v0 *= inv; v1 *= inv; v2 *= inv; v3 *= inv; v4 *= inv;
                }
                float v = (g == 0) ? v0 : (g == 1) ? v1 : (g == 2) ? v2
                                        : (g == 3) ? v3 : v4;
                hh[e] = __half_as_ushort(__float2half_rn(v));
            }
            hp[u] = (uint32_t)hh[0] | ((uint32_t)hh[1] << 16);
        }
        int off = rowbyte + q * 16;
        int sw  = off ^ ((off >> 3) & 0x70);
        *reinterpret_cast<uint4*>(tA + sw) = make_uint4(hp[0], hp[1], hp[2], hp[3]);
    }
}

// Producers (256 threads): B via cp.async (overlaps A basis gen)
__device__ __forceinline__ void produce_B(uint32_t stage_u32, int kt, int n0,
                                          int t) {
    const char* wh = reinterpret_cast<const char*>(g_Wh) +
                     (size_t)n0 * (KDIM * 2) + kt * 128;
    const char* wl = reinterpret_cast<const char*>(g_Wl) +
                     (size_t)n0 * (KDIM * 2) + kt * 128;
#pragma unroll
    for (int z = 0; z < 4; z++) {
        int c   = t + z * NTHR;           // 0..1023
        int n   = c >> 3;                 // 0..127
        int k16 = c & 7;
        size_t gb = (size_t)n * (KDIM * 2) + k16 * 16;
        int off = n * 128 + k16 * 16;
        int sw  = off ^ ((off >> 3) & 0x70);
        cp_async16(stage_u32 + OFF_BH + sw, wh + gb);
        cp_async16(stage_u32 + OFF_BL + sw, wl + gb);
    }
    CP_COMMIT();
}

__device__ __forceinline__ void produce_A(char* stage, int kt, int half,
                                          int rowbyte,
                                          const float* __restrict__ xr,
                                          float s, float tt,
                                          float g0, float g1, float g2,
                                          float g3, float g4) {
    int ks = kt * KT_W + half * 32;
    int i0 = ks / 5;
    switch (ks % 5) {
    case 0: gen_span<0>(xr, i0, s, tt, g0, g1, g2, g3, g4,
                        stage + OFF_A, rowbyte); break;
    case 1: gen_span<1>(xr, i0, s, tt, g0, g1, g2, g3, g4,
                        stage + OFF_A, rowbyte); break;
    case 2: gen_span<2>(xr, i0, s, tt, g0, g1, g2, g3, g4,
                        stage + OFF_A, rowbyte); break;
    case 3: gen_span<3>(xr, i0, s, tt, g0, g1, g2, g3, g4,
                        stage + OFF_A, rowbyte); break;
    default: gen_span<4>(xr, i0, s, tt, g0, g1, g2, g3, g4,
                         stage + OFF_A, rowbyte); break;
    }
}

// ---------------------------------------------------------------------------
// Main kernel: per-CTA 128x128 GEMM over K=1280 (20 tiles of 64),
// 2 fp16 passes into ONE fp32 accumulator set (a*wh + a*wl),
// mma.sync.m16n8k16.f16, occupancy 2.
// 8 warps, warp tile 64M x 32N (4 M-frags x 4 N-frags):
//   per k16: 4 A-ldsm_x4 + 8 B-ldsm_x2 feed 32 mma (128 B/mma).
// Swizzle handled per-access: addr = base + ((off0 + ks*32) ^ m) + frag*const,
// where m = ((off0>>3)&0x70) is invariant in ks/frag (row%8 unchanged) and
// off0+ks*32 never carries into bits [7+].
// ---------------------------------------------------------------------------
__global__ void __launch_bounds__(NTHR, 2)
kan_mma_kernel(const float* __restrict__ x, const float* __restrict__ grid,
               const float* __restrict__ bias, float* __restrict__ out) {
    extern __shared__ char dsm[];
    const uint32_t sb = smem_u32(dsm);
    const int t = threadIdx.x;
    const int rowBase = blockIdx.x * BM;
    const int n0      = blockIdx.y * BN;

    const float s  = g_st[0];
    const float tt = g_st[1];
    const float gr0 = __ldg(grid + 0), gr1 = __ldg(grid + 1),
                gr2 = __ldg(grid + 2), gr3 = __ldg(grid + 3),
                gr4 = __ldg(grid + 4);

    // Producer mapping: thread -> (row, 32-col half)
    const int r       = t & 127;
    const int half    = t >> 7;           // 0..1
    const int rowbyte = r * 128 + half * 64;
    const float* xr   = x + (size_t)(rowBase + r) * NIN;

    // Consumer mapping: warp = (mw, nw); tile 64 rows x 32 cols
    const int w = t >> 5, lane = t & 31;
    const int mw = w >> 2;                // 0..1   (64-row group)
    const int nw = w & 3;                 // 0..3   (32-col group)

    // Raw (unswizzled) per-lane offsets + invariant swizzle masks
    const uint32_t a_off0 = (uint32_t)((mw * 64 + (lane & 15)) * 128 +
                                       (lane >> 4) * 16);
    const uint32_t a_m    = (a_off0 >> 3) & 0x70;
    const uint32_t b_off0 = (uint32_t)((nw * 32 + (lane & 7)) * 128 +
                                       ((lane >> 3) & 1) * 16);
    const uint32_t b_m    = (b_off0 >> 3) & 0x70;

    const uint32_t aBase  = sb + SM_DATA + OFF_A;
    const uint32_t bhBase = sb + SM_DATA + OFF_BH;
    const uint32_t blBase = sb + SM_DATA + OFF_BL;

    float acc[4][4][4];   // [m-frag][n-frag][4], shared by hi+lo passes
#pragma unroll
    for (int mg = 0; mg < 4; mg++)
#pragma unroll
        for (int nb = 0; nb < 4; nb++)
#pragma unroll
            for (int j = 0; j < 4; j++) acc[mg][nb][j] = 0.0f;

    char* stage = dsm + SM_DATA;

    for (int kt = 0; kt < NT; kt++) {
        produce_B(sb + SM_DATA, kt, n0, t);
        produce_A(stage, kt, half, rowbyte, xr, s, tt, gr0, gr1, gr2, gr3, gr4);
        CP_WAIT0();
        __syncthreads();

#pragma unroll
        for (int ks = 0; ks < 4; ks++) {
            const uint32_t asw = (a_off0 + ks * 32) ^ a_m;
            const uint32_t bsw = (b_off0 + ks * 32) ^ b_m;

            uint32_t a[4][4];
#pragma unroll
            for (int mg = 0; mg < 4; mg++)
                ldsm_x4(a[mg], aBase + asw + mg * 2048);

            uint32_t bf[2];
#pragma unroll
            for (int nb = 0; nb < 4; nb++) {
                ldsm_x2(bf, bhBase + bsw + nb * 1024);
#pragma unroll
                for (int mg = 0; mg < 4; mg++)
                    mma_16816(acc[mg][nb], a[mg], bf);
            }
#pragma unroll
            for (int nb = 0; nb < 4; nb++) {
                ldsm_x2(bf, blBase + bsw + nb * 1024);
#pragma unroll
                for (int mg = 0; mg < 4; mg++)
                    mma_16816(acc[mg][nb], a[mg], bf);
            }
        }
        __syncthreads();
    }

    // ---- epilogue: add bias, store ----
    {
        const int er = lane >> 2;
        const int ec = (lane & 3) * 2;
#pragma unroll
        for (int mg = 0; mg < 4; mg++) {
            const size_t row0 = (size_t)(rowBase + mw * 64 + mg * 16 + er);
#pragma unroll
            for (int nb = 0; nb < 4; nb++) {
                int c = n0 + (nw * 4 + nb) * 8 + ec;
                float2 b2 = *reinterpret_cast<const float2*>(bias + c);
                float2 v0, v1;
                v0.x = acc[mg][nb][0] + b2.x;
                v0.y = acc[mg][nb][1] + b2.y;
                v1.x = acc[mg][nb][2] + b2.x;
                v1.y = acc[mg][nb][3] + b2.y;
                *reinterpret_cast<float2*>(out + row0 * NOUT + c) = v0;
                *reinterpret_cast<float2*>(out + (row0 + 8) * NOUT + c) = v1;
            }
        }
    }
}

// ---------------------------------------------------------------------------
extern "C" void kernel_launch(void* const* d_in, const int* in_sizes, int n_in,
                              void* d_out, int out_size) {
    const float* x     = (const float*)d_in[0];
    const float* grid  = (const float*)d_in[1];
    const float* coef  = (const float*)d_in[2];
    const float* scale = (const float*)d_in[3];
    const float* bias  = (const float*)d_in[4];
    float* out = (float*)d_out;

    int n = in_sizes[0];
    minmax_part_kernel<<<256, 256>>>(x, n / 4);
    minmax_final_kernel<<<1, 256>>>();
    wprep_kernel<<<(NOUT * KDIM + 255) / 256, 256>>>(coef, scale);

    cudaFuncSetAttribute(kan_mma_kernel,
                         cudaFuncAttributeMaxDynamicSharedMemorySize,
                         SMEM_TOTAL);
    dim3 g(BATCH / BM, NOUT / BN);
    kan_mma_kernel<<<g, NTHR, SMEM_TOTAL>>>(x, grid, bias, out);
}

// round 11
// speedup vs baseline: 1.5027x; 1.2230x over previous
#include <cuda_runtime.h>
#include <cuda_fp16.h>
#include <cstdint>

#define G_EPS 1e-8f

#define BATCH 32768
#define NIN   256
#define NOUT  256
#define NG    5
#define KDIM  (NIN * NG)      // 1280

#define KT_W  64              // K columns per tile (64 fp16 = 128B SW128 row)
#define NT    (KDIM / KT_W)   // 20 K-tiles
#define BM    128             // M rows per CTA
#define BN    128             // N cols per CTA
#define NTHR  256             // 8 warps

// SMEM: two stages, each A 16KB + B 16KB
#define OFF_A  0
#define OFF_B  16384
#define STAGE  32768
#define SM_DATA 1024
#define SMEM_TOTAL (SM_DATA + 2 * STAGE)   // 66560 -> 2 CTAs/SM

__device__ float g_pmin[256];
__device__ float g_pmax[256];
__device__ float g_st[2];   // s, t for xn = s*x + t
__device__ __align__(16) __half g_Wh[NOUT * KDIM];

// ---------------------------------------------------------------------------
// Helpers
// ---------------------------------------------------------------------------
__device__ __forceinline__ uint32_t smem_u32(const void* p) {
    uint32_t a;
    asm("{ .reg .u64 t; cvta.to.shared.u64 t, %1; cvt.u32.u64 %0, t; }"
        : "=r"(a) : "l"(p));
    return a;
}
__device__ __forceinline__ void cp_async16(uint32_t dst, const void* src) {
    asm volatile("cp.async.cg.shared.global [%0], [%1], 16;"
                 :: "r"(dst), "l"(src) : "memory");
}
#define CP_COMMIT() asm volatile("cp.async.commit_group;" ::: "memory")
#define CP_WAIT0()  asm volatile("cp.async.wait_group 0;" ::: "memory")

__device__ __forceinline__ void ldsm_x4(uint32_t* r, uint32_t addr) {
    asm volatile("ldmatrix.sync.aligned.m8n8.x4.shared.b16 {%0,%1,%2,%3}, [%4];"
                 : "=r"(r[0]), "=r"(r[1]), "=r"(r[2]), "=r"(r[3]) : "r"(addr));
}
__device__ __forceinline__ void ldsm_x2(uint32_t* r, uint32_t addr) {
    asm volatile("ldmatrix.sync.aligned.m8n8.x2.shared.b16 {%0,%1}, [%2];"
                 : "=r"(r[0]), "=r"(r[1]) : "r"(addr));
}
__device__ __forceinline__ void mma_16816(float* d, const uint32_t* a,
                                          const uint32_t* b) {
    asm volatile(
        "mma.sync.aligned.m16n8k16.row.col.f32.f16.f16.f32 "
        "{%0,%1,%2,%3}, {%4,%5,%6,%7}, {%8,%9}, {%0,%1,%2,%3};"
        : "+f"(d[0]), "+f"(d[1]), "+f"(d[2]), "+f"(d[3])
        : "r"(a[0]), "r"(a[1]), "r"(a[2]), "r"(a[3]), "r"(b[0]), "r"(b[1]));
}

// ---------------------------------------------------------------------------
// Kernel 1/2: global min/max reduction
// ---------------------------------------------------------------------------
__global__ void minmax_part_kernel(const float* __restrict__ x, int n4) {
    const float4* x4 = reinterpret_cast<const float4*>(x);
    float mn = 3.402823466e38f, mx = -3.402823466e38f;
    for (int i = blockIdx.x * blockDim.x + threadIdx.x; i < n4;
         i += gridDim.x * blockDim.x) {
        float4 v = x4[i];
        mn = fminf(mn, fminf(fminf(v.x, v.y), fminf(v.z, v.w)));
        mx = fmaxf(mx, fmaxf(fmaxf(v.x, v.y), fmaxf(v.z, v.w)));
    }
#pragma unroll
    for (int o = 16; o > 0; o >>= 1) {
        mn = fminf(mn, __shfl_xor_sync(0xffffffffu, mn, o));
        mx = fmaxf(mx, __shfl_xor_sync(0xffffffffu, mx, o));
    }
    __shared__ float smn[8], smx[8];
    int wid = threadIdx.x >> 5, lane = threadIdx.x & 31;
    if (lane == 0) { smn[wid] = mn; smx[wid] = mx; }
    __syncthreads();
    if (threadIdx.x < 8) {
        mn = smn[threadIdx.x];
        mx = smx[threadIdx.x];
#pragma unroll
        for (int o = 4; o > 0; o >>= 1) {
            mn = fminf(mn, __shfl_xor_sync(0xffu, mn, o));
            mx = fmaxf(mx, __shfl_xor_sync(0xffu, mx, o));
        }
        if (threadIdx.x == 0) { g_pmin[blockIdx.x] = mn; g_pmax[blockIdx.x] = mx; }
    }
}

__global__ void minmax_final_kernel() {
    int t = threadIdx.x;
    float mn = g_pmin[t], mx = g_pmax[t];
#pragma unroll
    for (int o = 16; o > 0; o >>= 1) {
        mn = fminf(mn, __shfl_xor_sync(0xffffffffu, mn, o));
        mx = fmaxf(mx, __shfl_xor_sync(0xffffffffu, mx, o));
    }
    __shared__ float smn[8], smx[8];
    int wid = t >> 5, lane = t & 31;
    if (lane == 0) { smn[wid] = mn; smx[wid] = mx; }
    __syncthreads();
    if (t < 8) {
        mn = smn[t];
        mx = smx[t];
#pragma unroll
        for (int o = 4; o > 0; o >>= 1) {
            mn = fminf(mn, __shfl_xor_sync(0xffu, mn, o));
            mx = fmaxf(mx, __shfl_xor_sync(0xffu, mx, o));
        }
        if (t == 0) {
            float range = mx - mn + G_EPS;
            g_st[0] = 2.0f / range;
            g_st[1] = -2.0f * mn / range - 1.0f;
        }
    }
}

// ---------------------------------------------------------------------------
// Kernel 3: W = coef*scale -> fp16
// ---------------------------------------------------------------------------
__global__ void wprep_kernel(const float* __restrict__ coef,
                             const float* __restrict__ scale) {
    int idx = blockIdx.x * blockDim.x + threadIdx.x;
    if (idx < NOUT * KDIM) {
        int o   = idx / KDIM;
        int rem = idx - o * KDIM;
        int i   = rem / NG;
        float w = coef[idx] * scale[o * NIN + i];
        g_Wh[idx] = __float2half_rn(w);
    }
}

// ---------------------------------------------------------------------------
// A-tile generation: 32 consecutive K columns of one row, fp16.
// Phase P0 = kstart % 5 is compile-time.
// ---------------------------------------------------------------------------
template <int P0>
__device__ __forceinline__ void gen_span(const float* __restrict__ xr, int i0,
                                         float s, float tt,
                                         float g0, float g1, float g2,
                                         float g3, float g4,
                                         char* tA, int rowbyte) {
    float v0 = 0.f, v1 = 0.f, v2 = 0.f, v3 = 0.f, v4 = 0.f;
    int i = i0;
#pragma unroll
    for (int q = 0; q < 4; q++) {
        uint32_t hp[4];
#pragma unroll
        for (int u = 0; u < 4; u++) {
            unsigned short hh[2];
#pragma unroll
            for (int e = 0; e < 2; e++) {
                const int j = q * 8 + u * 2 + e;
                const int g = (P0 + j) % 5;
                if (g == 0 || j == 0) {
                    if (g == 0 && j > 0) i++;
                    float xv = __ldg(xr + i);
                    float xn = fmaf(xv, s, tt);
                    float d;
                    d = fabsf(xn - g0); v0 = fmaxf(fmaf(-d * d, d, 1.0f), 0.0f);
                    d = fabsf(xn - g1); v1 = fmaxf(fmaf(-d * d, d, 1.0f), 0.0f);
                    d = fabsf(xn - g2); v2 = fmaxf(fmaf(-d * d, d, 1.0f), 0.0f);
                    d = fabsf(xn - g3); v3 = fmaxf(fmaf(-d * d, d, 1.0f), 0.0f);
                    d = fabsf(xn - g4); v4 = fmaxf(fmaf(-d * d, d, 1.0f), 0.0f);
                    float inv = __fdividef(1.0f, v0 + v1 + v2 + v3 + v4 + G_EPS);
                    v0 *= inv; v1 *= inv; v2 *= inv; v3 *= inv; v4 *= inv;
                }
                float v = (g == 0) ? v0 : (g == 1) ? v1 : (g == 2) ? v2
                                        : (g == 3) ? v3 : v4;
                hh[e] = __half_as_ushort(__float2half_rn(v));
            }
            hp[u] = (uint32_t)hh[0] | ((uint32_t)hh[1] << 16);
        }
        int off = rowbyte + q * 16;
        int sw  = off ^ ((off >> 3) & 0x70);
        *reinterpret_cast<uint4*>(tA + sw) = make_uint4(hp[0], hp[1], hp[2], hp[3]);
    }
}

// Producers (256 threads)
__device__ __forceinline__ void produce_B(uint32_t stage_u32, int kt, int n0,
                                          int t) {
    const char* wh = reinterpret_cast<const char*>(g_Wh) +
                     (size_t)n0 * (KDIM * 2) + kt * 128;
#pragma unroll
    for (int z = 0; z < 4; z++) {
        int c   = t + z * NTHR;           // 0..1023
        int n   = c >> 3;                 // 0..127
        int k16 = c & 7;
        size_t gb = (size_t)n * (KDIM * 2) + k16 * 16;
        int off = n * 128 + k16 * 16;
        int sw  = off ^ ((off >> 3) & 0x70);
        cp_async16(stage_u32 + OFF_B + sw, wh + gb);
    }
    CP_COMMIT();
}

__device__ __forceinline__ void produce_A(char* stage, int kt, int half,
                                          int rowbyte,
                                          const float* __restrict__ xr,
                                          float s, float tt,
                                          float g0, float g1, float g2,
                                          float g3, float g4) {
    int ks = kt * KT_W + half * 32;
    int i0 = ks / 5;
    switch (ks % 5) {
    case 0: gen_span<0>(xr, i0, s, tt, g0, g1, g2, g3, g4,
                        stage + OFF_A, rowbyte); break;
    case 1: gen_span<1>(xr, i0, s, tt, g0, g1, g2, g3, g4,
                        stage + OFF_A, rowbyte); break;
    case 2: gen_span<2>(xr, i0, s, tt, g0, g1, g2, g3, g4,
                        stage + OFF_A, rowbyte); break;
    case 3: gen_span<3>(xr, i0, s, tt, g0, g1, g2, g3, g4,
                        stage + OFF_A, rowbyte); break;
    default: gen_span<4>(xr, i0, s, tt, g0, g1, g2, g3, g4,
                         stage + OFF_A, rowbyte); break;
    }
}

// ---------------------------------------------------------------------------
// Main kernel: per-CTA 128x128 GEMM over K=1280 (20 tiles of 64),
// SINGLE fp16 pass, double-buffered pipeline:
//   per tile: issue cp.async B(kt+1) -> A-gen(kt+1) -> MMA(kt) -> wait -> sync
// 8 warps, warp tile 64M x 32N, occupancy 2.
// ---------------------------------------------------------------------------
__global__ void __launch_bounds__(NTHR, 2)
kan_mma_kernel(const float* __restrict__ x, const float* __restrict__ grid,
               const float* __restrict__ bias, float* __restrict__ out) {
    extern __shared__ char dsm[];
    const uint32_t sb = smem_u32(dsm);
    const int t = threadIdx.x;
    const int rowBase = blockIdx.x * BM;
    const int n0      = blockIdx.y * BN;

    const float s  = g_st[0];
    const float tt = g_st[1];
    const float gr0 = __ldg(grid + 0), gr1 = __ldg(grid + 1),
                gr2 = __ldg(grid + 2), gr3 = __ldg(grid + 3),
                gr4 = __ldg(grid + 4);

    // Producer mapping: thread -> (row, 32-col half)
    const int r       = t & 127;
    const int half    = t >> 7;           // 0..1
    const int rowbyte = r * 128 + half * 64;
    const float* xr   = x + (size_t)(rowBase + r) * NIN;

    // Consumer mapping: warp = (mw, nw); tile 64 rows x 32 cols
    const int w = t >> 5, lane = t & 31;
    const int mw = w >> 2;                // 0..1   (64-row group)
    const int nw = w & 3;                 // 0..3   (32-col group)

    // Raw (unswizzled) per-lane offsets + invariant swizzle masks
    const uint32_t a_off0 = (uint32_t)((mw * 64 + (lane & 15)) * 128 +
                                       (lane >> 4) * 16);
    const uint32_t a_m    = (a_off0 >> 3) & 0x70;
    const uint32_t b_off0 = (uint32_t)((nw * 32 + (lane & 7)) * 128 +
                                       ((lane >> 3) & 1) * 16);
    const uint32_t b_m    = (b_off0 >> 3) & 0x70;

    float acc[4][4][4];   // [m-frag][n-frag][4]
#pragma unroll
    for (int mg = 0; mg < 4; mg++)
#pragma unroll
        for (int nb = 0; nb < 4; nb++)
#pragma unroll
            for (int j = 0; j < 4; j++) acc[mg][nb][j] = 0.0f;

    // Prologue: produce tile 0 into stage 0
    produce_B(sb + SM_DATA, 0, n0, t);
    produce_A(dsm + SM_DATA, 0, half, rowbyte, xr, s, tt,
              gr0, gr1, gr2, gr3, gr4);
    CP_WAIT0();
    __syncthreads();

    for (int kt = 0; kt < NT; kt++) {
        const int b = kt & 1;
        const uint32_t cbase = sb + SM_DATA + b * STAGE;

        // ---- produce next tile into the other stage (overlaps MMA) ----
        if (kt + 1 < NT) {
            const uint32_t pbase = sb + SM_DATA + (1 - b) * STAGE;
            produce_B(pbase, kt + 1, n0, t);
            produce_A(dsm + SM_DATA + (1 - b) * STAGE, kt + 1, half, rowbyte,
                      xr, s, tt, gr0, gr1, gr2, gr3, gr4);
        }

        // ---- consume current tile ----
#pragma unroll
        for (int ks = 0; ks < 4; ks++) {
            const uint32_t asw = (a_off0 + ks * 32) ^ a_m;
            const uint32_t bsw = (b_off0 + ks * 32) ^ b_m;

            uint32_t a[4][4];
#pragma unroll
            for (int mg = 0; mg < 4; mg++)
                ldsm_x4(a[mg], cbase + OFF_A + asw + mg * 2048);

            uint32_t bf[4][2];
#pragma unroll
            for (int nb = 0; nb < 4; nb++)
                ldsm_x2(bf[nb], cbase + OFF_B + bsw + nb * 1024);

#pragma unroll
            for (int mg = 0; mg < 4; mg++)
#pragma unroll
                for (int nb = 0; nb < 4; nb++)
                    mma_16816(acc[mg][nb], a[mg], bf[nb]);
        }

        if (kt + 1 < NT) CP_WAIT0();
        __syncthreads();
    }

    // ---- epilogue: add bias, store ----
    {
        const int er = lane >> 2;
        const int ec = (lane & 3) * 2;
#pragma unroll
        for (int mg = 0; mg < 4; mg++) {
            const size_t row0 = (size_t)(rowBase + mw * 64 + mg * 16 + er);
#pragma unroll
            for (int nb = 0; nb < 4; nb++) {
                int c = n0 + (nw * 4 + nb) * 8 + ec;
                float2 b2 = *reinterpret_cast<const float2*>(bias + c);
                float2 v0, v1;
                v0.x = acc[mg][nb][0] + b2.x;
                v0.y = acc[mg][nb][1] + b2.y;
                v1.x = acc[mg][nb][2] + b2.x;
                v1.y = acc[mg][nb][3] + b2.y;
                *reinterpret_cast<float2*>(out + row0 * NOUT + c) = v0;
                *reinterpret_cast<float2*>(out + (row0 + 8) * NOUT + c) = v1;
            }
        }
    }
}

// ---------------------------------------------------------------------------
extern "C" void kernel_launch(void* const* d_in, const int* in_sizes, int n_in,
                              void* d_out, int out_size) {
    const float* x     = (const float*)d_in[0];
    const float* grid  = (const float*)d_in[1];
    const float* coef  = (const float*)d_in[2];
    const float* scale = (const float*)d_in[3];
    const float* bias  = (const float*)d_in[4];
    float* out = (float*)d_out;

    int n = in_sizes[0];
    minmax_part_kernel<<<256, 256>>>(x, n / 4);
    minmax_final_kernel<<<1, 256>>>();
    wprep_kernel<<<(NOUT * KDIM + 255) / 256, 256>>>(coef, scale);

    cudaFuncSetAttribute(kan_mma_kernel,
                         cudaFuncAttributeMaxDynamicSharedMemorySize,
                         SMEM_TOTAL);
    dim3 g(BATCH / BM, NOUT / BN);
    kan_mma_kernel<<<g, NTHR, SMEM_TOTAL>>>(x, grid, bias, out);
}

// round 12
// speedup vs baseline: 1.9418x; 1.2922x over previous
#include <cuda_runtime.h>
#include <cuda_fp16.h>
#include <cstdint>

#define G_EPS 1e-8f

#define BATCH 32768
#define NIN   256
#define NOUT  256
#define NG    5
#define KDIM  (NIN * NG)      // 1280

#define KT_W  64              // K columns per tile (64 fp16 = 128B SW128 row)
#define NT    (KDIM / KT_W)   // 20 K-tiles
#define BM    128             // M rows per CTA
#define BN    128             // N cols per CTA
#define NTHR  256             // 8 warps

// SMEM: two stages, each A 16KB + B 16KB
#define OFF_A  0
#define OFF_B  16384
#define STAGE  32768
#define SM_DATA 1024
#define SMEM_TOTAL (SM_DATA + 2 * STAGE)   // 66560 -> 2 CTAs/SM

__device__ float g_pmin[256];
__device__ float g_pmax[256];
__device__ float g_st[2];   // s, t for xn = s*x + t
__device__ __align__(16) __half g_Wh[NOUT * KDIM];
__device__ __align__(16) __half g_A[(size_t)BATCH * KDIM];   // 80 MB basis

// ---------------------------------------------------------------------------
// Helpers
// ---------------------------------------------------------------------------
__device__ __forceinline__ uint32_t smem_u32(const void* p) {
    uint32_t a;
    asm("{ .reg .u64 t; cvta.to.shared.u64 t, %1; cvt.u32.u64 %0, t; }"
        : "=r"(a) : "l"(p));
    return a;
}
__device__ __forceinline__ void cp_async16(uint32_t dst, const void* src) {
    asm volatile("cp.async.cg.shared.global [%0], [%1], 16;"
                 :: "r"(dst), "l"(src) : "memory");
}
#define CP_COMMIT() asm volatile("cp.async.commit_group;" ::: "memory")
#define CP_WAIT0()  asm volatile("cp.async.wait_group 0;" ::: "memory")

__device__ __forceinline__ void ldsm_x4(uint32_t* r, uint32_t addr) {
    asm volatile("ldmatrix.sync.aligned.m8n8.x4.shared.b16 {%0,%1,%2,%3}, [%4];"
                 : "=r"(r[0]), "=r"(r[1]), "=r"(r[2]), "=r"(r[3]) : "r"(addr));
}
__device__ __forceinline__ void ldsm_x2(uint32_t* r, uint32_t addr) {
    asm volatile("ldmatrix.sync.aligned.m8n8.x2.shared.b16 {%0,%1}, [%2];"
                 : "=r"(r[0]), "=r"(r[1]) : "r"(addr));
}
__device__ __forceinline__ void mma_16816(float* d, const uint32_t* a,
                                          const uint32_t* b) {
    asm volatile(
        "mma.sync.aligned.m16n8k16.row.col.f32.f16.f16.f32 "
        "{%0,%1,%2,%3}, {%4,%5,%6,%7}, {%8,%9}, {%0,%1,%2,%3};"
        : "+f"(d[0]), "+f"(d[1]), "+f"(d[2]), "+f"(d[3])
        : "r"(a[0]), "r"(a[1]), "r"(a[2]), "r"(a[3]), "r"(b[0]), "r"(b[1]));
}

// ---------------------------------------------------------------------------
// Kernel 1/2: global min/max reduction
// ---------------------------------------------------------------------------
__global__ void minmax_part_kernel(const float* __restrict__ x, int n4) {
    const float4* x4 = reinterpret_cast<const float4*>(x);
    float mn = 3.402823466e38f, mx = -3.402823466e38f;
    for (int i = blockIdx.x * blockDim.x + threadIdx.x; i < n4;
         i += gridDim.x * blockDim.x) {
        float4 v = x4[i];
        mn = fminf(mn, fminf(fminf(v.x, v.y), fminf(v.z, v.w)));
        mx = fmaxf(mx, fmaxf(fmaxf(v.x, v.y), fmaxf(v.z, v.w)));
    }
#pragma unroll
    for (int o = 16; o > 0; o >>= 1) {
        mn = fminf(mn, __shfl_xor_sync(0xffffffffu, mn, o));
        mx = fmaxf(mx, __shfl_xor_sync(0xffffffffu, mx, o));
    }
    __shared__ float smn[8], smx[8];
    int wid = threadIdx.x >> 5, lane = threadIdx.x & 31;
    if (lane == 0) { smn[wid] = mn; smx[wid] = mx; }
    __syncthreads();
    if (threadIdx.x < 8) {
        mn = smn[threadIdx.x];
        mx = smx[threadIdx.x];
#pragma unroll
        for (int o = 4; o > 0; o >>= 1) {
            mn = fminf(mn, __shfl_xor_sync(0xffu, mn, o));
            mx = fmaxf(mx, __shfl_xor_sync(0xffu, mx, o));
        }
        if (threadIdx.x == 0) { g_pmin[blockIdx.x] = mn; g_pmax[blockIdx.x] = mx; }
    }
}

__global__ void minmax_final_kernel() {
    int t = threadIdx.x;
    float mn = g_pmin[t], mx = g_pmax[t];
#pragma unroll
    for (int o = 16; o > 0; o >>= 1) {
        mn = fminf(mn, __shfl_xor_sync(0xffffffffu, mn, o));
        mx = fmaxf(mx, __shfl_xor_sync(0xffffffffu, mx, o));
    }
    __shared__ float smn[8], smx[8];
    int wid = t >> 5, lane = t & 31;
    if (lane == 0) { smn[wid] = mn; smx[wid] = mx; }
    __syncthreads();
    if (t < 8) {
        mn = smn[t];
        mx = smx[t];
#pragma unroll
        for (int o = 4; o > 0; o >>= 1) {
            mn = fminf(mn, __shfl_xor_sync(0xffu, mn, o));
            mx = fmaxf(mx, __shfl_xor_sync(0xffu, mx, o));
        }
        if (t == 0) {
            float range = mx - mn + G_EPS;
            g_st[0] = 2.0f / range;
            g_st[1] = -2.0f * mn / range - 1.0f;
        }
    }
}

// ---------------------------------------------------------------------------
// Kernel 3: W = coef*scale -> fp16
// ---------------------------------------------------------------------------
__global__ void wprep_kernel(const float* __restrict__ coef,
                             const float* __restrict__ scale) {
    int idx = blockIdx.x * blockDim.x + threadIdx.x;
    if (idx < NOUT * KDIM) {
        int o   = idx / KDIM;
        int rem = idx - o * KDIM;
        int i   = rem / NG;
        float w = coef[idx] * scale[o * NIN + i];
        g_Wh[idx] = __float2half_rn(w);
    }
}

// ---------------------------------------------------------------------------
// Kernel 4: basis matrix A[b][i*5+g] (fp16), 8 x-values per thread.
// 8 x -> 40 fp16 = 80 bytes = 5 aligned uint4 stores.
// ---------------------------------------------------------------------------
__global__ void __launch_bounds__(256)
basis_kernel(const float* __restrict__ x, const float* __restrict__ grid) {
    const size_t idx = (size_t)blockIdx.x * blockDim.x + threadIdx.x;
    const size_t ii  = idx * 8;                  // first x element
    if (ii >= (size_t)BATCH * NIN) return;

    const float s  = g_st[0];
    const float tt = g_st[1];
    const float g0 = __ldg(grid + 0), g1 = __ldg(grid + 1),
                g2 = __ldg(grid + 2), g3 = __ldg(grid + 3),
                g4 = __ldg(grid + 4);

    float4 xa = *reinterpret_cast<const float4*>(x + ii);
    float4 xb = *reinterpret_cast<const float4*>(x + ii + 4);
    float xe[8] = {xa.x, xa.y, xa.z, xa.w, xb.x, xb.y, xb.z, xb.w};

    unsigned short h[40];
#pragma unroll
    for (int e = 0; e < 8; e++) {
        float xn = fmaf(xe[e], s, tt);
        float d, v0, v1, v2, v3, v4;
        d = fabsf(xn - g0); v0 = fmaxf(fmaf(-d * d, d, 1.0f), 0.0f);
        d = fabsf(xn - g1); v1 = fmaxf(fmaf(-d * d, d, 1.0f), 0.0f);
        d = fabsf(xn - g2); v2 = fmaxf(fmaf(-d * d, d, 1.0f), 0.0f);
        d = fabsf(xn - g3); v3 = fmaxf(fmaf(-d * d, d, 1.0f), 0.0f);
        d = fabsf(xn - g4); v4 = fmaxf(fmaf(-d * d, d, 1.0f), 0.0f);
        float inv = __fdividef(1.0f, v0 + v1 + v2 + v3 + v4 + G_EPS);
        h[e * 5 + 0] = __half_as_ushort(__float2half_rn(v0 * inv));
        h[e * 5 + 1] = __half_as_ushort(__float2half_rn(v1 * inv));
        h[e * 5 + 2] = __half_as_ushort(__float2half_rn(v2 * inv));
        h[e * 5 + 3] = __half_as_ushort(__float2half_rn(v3 * inv));
        h[e * 5 + 4] = __half_as_ushort(__float2half_rn(v4 * inv));
    }

    uint4* dst = reinterpret_cast<uint4*>(
        reinterpret_cast<char*>(g_A) + ii * 10);   // 5 fp16 per x = 10 B
#pragma unroll
    for (int q = 0; q < 5; q++) {
        uint4 v;
        v.x = (uint32_t)h[q * 8 + 0] | ((uint32_t)h[q * 8 + 1] << 16);
        v.y = (uint32_t)h[q * 8 + 2] | ((uint32_t)h[q * 8 + 3] << 16);
        v.z = (uint32_t)h[q * 8 + 4] | ((uint32_t)h[q * 8 + 5] << 16);
        v.w = (uint32_t)h[q * 8 + 6] | ((uint32_t)h[q * 8 + 7] << 16);
        dst[q] = v;
    }
}

// ---------------------------------------------------------------------------
// Producers (256 threads): pure cp.async for both A and B (same addressing,
// both row-major with 2560-byte row stride).
// ---------------------------------------------------------------------------
__device__ __forceinline__ void produce_tile(uint32_t stage_u32, int kt,
                                             const char* __restrict__ aRowBase,
                                             const char* __restrict__ bRowBase,
                                             int t) {
    const char* ag = aRowBase + kt * 128;
    const char* bg = bRowBase + kt * 128;
#pragma unroll
    for (int z = 0; z < 4; z++) {
        int c   = t + z * NTHR;           // 0..1023
        int n   = c >> 3;                 // row 0..127
        int k16 = c & 7;
        size_t gb = (size_t)n * (KDIM * 2) + k16 * 16;
        int off = n * 128 + k16 * 16;
        int sw  = off ^ ((off >> 3) & 0x70);
        cp_async16(stage_u32 + OFF_A + sw, ag + gb);
        cp_async16(stage_u32 + OFF_B + sw, bg + gb);
    }
    CP_COMMIT();
}

// ---------------------------------------------------------------------------
// Main kernel: per-CTA 128x128 GEMM over K=1280 (20 tiles of 64),
// single fp16 pass, pure cp.async double-buffered pipeline.
// 8 warps, warp tile 64M x 32N, occupancy 2.
// ---------------------------------------------------------------------------
__global__ void __launch_bounds__(NTHR, 2)
kan_mma_kernel(const float* __restrict__ bias, float* __restrict__ out) {
    extern __shared__ char dsm[];
    const uint32_t sb = smem_u32(dsm);
    const int t = threadIdx.x;
    const int rowBase = blockIdx.x * BM;
    const int n0      = blockIdx.y * BN;

    const char* aRowBase = reinterpret_cast<const char*>(g_A) +
                           (size_t)rowBase * (KDIM * 2);
    const char* bRowBase = reinterpret_cast<const char*>(g_Wh) +
                           (size_t)n0 * (KDIM * 2);

    // Consumer mapping: warp = (mw, nw); tile 64 rows x 32 cols
    const int w = t >> 5, lane = t & 31;
    const int mw = w >> 2;                // 0..1   (64-row group)
    const int nw = w & 3;                 // 0..3   (32-col group)

    const uint32_t a_off0 = (uint32_t)((mw * 64 + (lane & 15)) * 128 +
                                       (lane >> 4) * 16);
    const uint32_t a_m    = (a_off0 >> 3) & 0x70;
    const uint32_t b_off0 = (uint32_t)((nw * 32 + (lane & 7)) * 128 +
                                       ((lane >> 3) & 1) * 16);
    const uint32_t b_m    = (b_off0 >> 3) & 0x70;

    float acc[4][4][4];
#pragma unroll
    for (int mg = 0; mg < 4; mg++)
#pragma unroll
        for (int nb = 0; nb < 4; nb++)
#pragma unroll
            for (int j = 0; j < 4; j++) acc[mg][nb][j] = 0.0f;

    // Prologue: produce tile 0 into stage 0
    produce_tile(sb + SM_DATA, 0, aRowBase, bRowBase, t);
    CP_WAIT0();
    __syncthreads();

    for (int kt = 0; kt < NT; kt++) {
        const int b = kt & 1;
        const uint32_t cbase = sb + SM_DATA + b * STAGE;

        // ---- produce next tile into the other stage (overlaps MMA) ----
        if (kt + 1 < NT)
            produce_tile(sb + SM_DATA + (1 - b) * STAGE, kt + 1,
                         aRowBase, bRowBase, t);

        // ---- consume current tile ----
#pragma unroll
        for (int ks = 0; ks < 4; ks++) {
            const uint32_t asw = (a_off0 + ks * 32) ^ a_m;
            const uint32_t bsw = (b_off0 + ks * 32) ^ b_m;

            uint32_t a[4][4];
#pragma unroll
            for (int mg = 0; mg < 4; mg++)
                ldsm_x4(a[mg], cbase + OFF_A + asw + mg * 2048);

            uint32_t bf[4][2];
#pragma unroll
            for (int nb = 0; nb < 4; nb++)
                ldsm_x2(bf[nb], cbase + OFF_B + bsw + nb * 1024);

#pragma unroll
            for (int mg = 0; mg < 4; mg++)
#pragma unroll
                for (int nb = 0; nb < 4; nb++)
                    mma_16816(acc[mg][nb], a[mg], bf[nb]);
        }

        if (kt + 1 < NT) CP_WAIT0();
        __syncthreads();
    }

    // ---- epilogue: add bias, store ----
    {
        const int er = lane >> 2;
        const int ec = (lane & 3) * 2;
#pragma unroll
        for (int mg = 0; mg < 4; mg++) {
            const size_t row0 = (size_t)(rowBase + mw * 64 + mg * 16 + er);
#pragma unroll
            for (int nb = 0; nb < 4; nb++) {
                int c = n0 + (nw * 4 + nb) * 8 + ec;
                float2 b2 = *reinterpret_cast<const float2*>(bias + c);
                float2 v0, v1;
                v0.x = acc[mg][nb][0] + b2.x;
                v0.y = acc[mg][nb][1] + b2.y;
                v1.x = acc[mg][nb][2] + b2.x;
                v1.y = acc[mg][nb][3] + b2.y;
                *reinterpret_cast<float2*>(out + row0 * NOUT + c) = v0;
                *reinterpret_cast<float2*>(out + (row0 + 8) * NOUT + c) = v1;
            }
        }
    }
}

// ---------------------------------------------------------------------------
extern "C" void kernel_launch(void* const* d_in, const int* in_sizes, int n_in,
                              void* d_out, int out_size) {
    const float* x     = (const float*)d_in[0];
    const float* grid  = (const float*)d_in[1];
    const float* coef  = (const float*)d_in[2];
    const float* scale = (const float*)d_in[3];
    const float* bias  = (const float*)d_in[4];
    float* out = (float*)d_out;

    int n = in_sizes[0];
    minmax_part_kernel<<<256, 256>>>(x, n / 4);
    minmax_final_kernel<<<1, 256>>>();
    wprep_kernel<<<(NOUT * KDIM + 255) / 256, 256>>>(coef, scale);
    basis_kernel<<<(BATCH * NIN / 8 + 255) / 256, 256>>>(x, grid);

    cudaFuncSetAttribute(kan_mma_kernel,
                         cudaFuncAttributeMaxDynamicSharedMemorySize,
                         SMEM_TOTAL);
    dim3 g(BATCH / BM, NOUT / BN);
    kan_mma_kernel<<<g, NTHR, SMEM_TOTAL>>>(bias, out);
}

// round 14
// speedup vs baseline: 2.0108x; 1.0356x over previous
#include <cuda_runtime.h>
#include <cuda_fp16.h>
#include <cstdint>

#define G_EPS 1e-8f

#define BATCH 32768
#define NIN   256
#define NOUT  256
#define NG    5
#define KDIM  (NIN * NG)      // 1280

#define KT_W  64              // K columns per tile (64 fp16 = 128B SW128 row)
#define NT    (KDIM / KT_W)   // 20 K-tiles
#define BM    128             // M rows per CTA
#define BN    128             // N cols per CTA
#define NTHR  512             // 16 warps

// SMEM: two stages, each A 16KB + B 16KB
#define OFF_A  0
#define OFF_B  16384
#define STAGE  32768
#define SM_DATA 1024
#define SMEM_TOTAL (SM_DATA + 2 * STAGE)   // 66560 -> 2 CTAs/SM

__device__ float g_pmin[256];
__device__ float g_pmax[256];
__device__ float g_st[2];   // s, t for xn = s*x + t
__device__ __align__(16) __half g_Wh[NOUT * KDIM];
__device__ __align__(16) __half g_A[(size_t)BATCH * KDIM];   // 80 MB basis

// ---------------------------------------------------------------------------
// Helpers
// ---------------------------------------------------------------------------
__device__ __forceinline__ uint32_t smem_u32(const void* p) {
    uint32_t a;
    asm("{ .reg .u64 t; cvta.to.shared.u64 t, %1; cvt.u32.u64 %0, t; }"
        : "=r"(a) : "l"(p));
    return a;
}
__device__ __forceinline__ void cp_async16(uint32_t dst, const void* src) {
    asm volatile("cp.async.cg.shared.global [%0], [%1], 16;"
                 :: "r"(dst), "l"(src) : "memory");
}
#define CP_COMMIT() asm volatile("cp.async.commit_group;" ::: "memory")
#define CP_WAIT0()  asm volatile("cp.async.wait_group 0;" ::: "memory")

__device__ __forceinline__ void ldsm_x4(uint32_t* r, uint32_t addr) {
    asm volatile("ldmatrix.sync.aligned.m8n8.x4.shared.b16 {%0,%1,%2,%3}, [%4];"
                 : "=r"(r[0]), "=r"(r[1]), "=r"(r[2]), "=r"(r[3]) : "r"(addr));
}
__device__ __forceinline__ void ldsm_x2(uint32_t* r, uint32_t addr) {
    asm volatile("ldmatrix.sync.aligned.m8n8.x2.shared.b16 {%0,%1}, [%2];"
                 : "=r"(r[0]), "=r"(r[1]) : "r"(addr));
}
__device__ __forceinline__ void mma_16816(float* d, const uint32_t* a,
                                          const uint32_t* b) {
    asm volatile(
        "mma.sync.aligned.m16n8k16.row.col.f32.f16.f16.f32 "
        "{%0,%1,%2,%3}, {%4,%5,%6,%7}, {%8,%9}, {%0,%1,%2,%3};"
        : "+f"(d[0]), "+f"(d[1]), "+f"(d[2]), "+f"(d[3])
        : "r"(a[0]), "r"(a[1]), "r"(a[2]), "r"(a[3]), "r"(b[0]), "r"(b[1]));
}

// ---------------------------------------------------------------------------
// Kernel 1/2: global min/max reduction
// ---------------------------------------------------------------------------
__global__ void minmax_part_kernel(const float* __restrict__ x, int n4) {
    const float4* x4 = reinterpret_cast<const float4*>(x);
    float mn = 3.402823466e38f, mx = -3.402823466e38f;
    for (int i = blockIdx.x * blockDim.x + threadIdx.x; i < n4;
         i += gridDim.x * blockDim.x) {
        float4 v = x4[i];
        mn = fminf(mn, fminf(fminf(v.x, v.y), fminf(v.z, v.w)));
        mx = fmaxf(mx, fmaxf(fmaxf(v.x, v.y), fmaxf(v.z, v.w)));
    }
#pragma unroll
    for (int o = 16; o > 0; o >>= 1) {
        mn = fminf(mn, __shfl_xor_sync(0xffffffffu, mn, o));
        mx = fmaxf(mx, __shfl_xor_sync(0xffffffffu, mx, o));
    }
    __shared__ float smn[8], smx[8];
    int wid = threadIdx.x >> 5, lane = threadIdx.x & 31;
    if (lane == 0) { smn[wid] = mn; smx[wid] = mx; }
    __syncthreads();
    if (threadIdx.x < 8) {
        mn = smn[threadIdx.x];
        mx = smx[threadIdx.x];
#pragma unroll
        for (int o = 4; o > 0; o >>= 1) {
            mn = fminf(mn, __shfl_xor_sync(0xffu, mn, o));
            mx = fmaxf(mx, __shfl_xor_sync(0xffu, mx, o));
        }
        if (threadIdx.x == 0) { g_pmin[blockIdx.x] = mn; g_pmax[blockIdx.x] = mx; }
    }
}

__global__ void minmax_final_kernel() {
    int t = threadIdx.x;
    float mn = g_pmin[t], mx = g_pmax[t];
#pragma unroll
    for (int o = 16; o > 0; o >>= 1) {
        mn = fminf(mn, __shfl_xor_sync(0xffffffffu, mn, o));
        mx = fmaxf(mx, __shfl_xor_sync(0xffffffffu, mx, o));
    }
    __shared__ float smn[8], smx[8];
    int wid = t >> 5, lane = t & 31;
    if (lane == 0) { smn[wid] = mn; smx[wid] = mx; }
    __syncthreads();
    if (t < 8) {
        mn = smn[t];
        mx = smx[t];
#pragma unroll
        for (int o = 4; o > 0; o >>= 1) {
            mn = fminf(mn, __shfl_xor_sync(0xffu, mn, o));
            mx = fmaxf(mx, __shfl_xor_sync(0xffu, mx, o));
        }
        if (t == 0) {
            float range = mx - mn + G_EPS;
            g_st[0] = 2.0f / range;
            g_st[1] = -2.0f * mn / range - 1.0f;
        }
    }
}

// ---------------------------------------------------------------------------
// Kernel 3: W = coef*scale -> fp16
// ---------------------------------------------------------------------------
__global__ void wprep_kernel(const float* __restrict__ coef,
                             const float* __restrict__ scale) {
    int idx = blockIdx.x * blockDim.x + threadIdx.x;
    if (idx < NOUT * KDIM) {
        int o   = idx / KDIM;
        int rem = idx - o * KDIM;
        int i   = rem / NG;
        float w = coef[idx] * scale[o * NIN + i];
        g_Wh[idx] = __float2half_rn(w);
    }
}

// ---------------------------------------------------------------------------
// Kernel 4: basis matrix A[b][i*5+g] (fp16), 8 x-values per thread.
// Compute into smem, then fully-coalesced uint4 copy-out.
// ---------------------------------------------------------------------------
__global__ void __launch_bounds__(256)
basis_kernel(const float* __restrict__ x, const float* __restrict__ grid) {
    __shared__ char sbuf[256 * 80];     // 20 KB staging
    const int t = threadIdx.x;
    const size_t blockX = (size_t)blockIdx.x * 2048;     // 256 thr * 8 x
    const size_t ii = blockX + (size_t)t * 8;

    const float s  = g_st[0];
    const float tt = g_st[1];
    const float g0 = __ldg(grid + 0), g1 = __ldg(grid + 1),
                g2 = __ldg(grid + 2), g3 = __ldg(grid + 3),
                g4 = __ldg(grid + 4);

    float4 xa = *reinterpret_cast<const float4*>(x + ii);
    float4 xb = *reinterpret_cast<const float4*>(x + ii + 4);
    float xe[8] = {xa.x, xa.y, xa.z, xa.w, xb.x, xb.y, xb.z, xb.w};

    unsigned short h[40];
#pragma unroll
    for (int e = 0; e < 8; e++) {
        float xn = fmaf(xe[e], s, tt);
        float d, v0, v1, v2, v3, v4;
        d = fabsf(xn - g0); v0 = fmaxf(fmaf(-d * d, d, 1.0f), 0.0f);
        d = fabsf(xn - g1); v1 = fmaxf(fmaf(-d * d, d, 1.0f), 0.0f);
        d = fabsf(xn - g2); v2 = fmaxf(fmaf(-d * d, d, 1.0f), 0.0f);
        d = fabsf(xn - g3); v3 = fmaxf(fmaf(-d * d, d, 1.0f), 0.0f);
        d = fabsf(xn - g4); v4 = fmaxf(fmaf(-d * d, d, 1.0f), 0.0f);
        float inv = __fdividef(1.0f, v0 + v1 + v2 + v3 + v4 + G_EPS);
        h[e * 5 + 0] = __half_as_ushort(__float2half_rn(v0 * inv));
        h[e * 5 + 1] = __half_as_ushort(__float2half_rn(v1 * inv));
        h[e * 5 + 2] = __half_as_ushort(__float2half_rn(v2 * inv));
        h[e * 5 + 3] = __half_as_ushort(__float2half_rn(v3 * inv));
        h[e * 5 + 4] = __half_as_ushort(__float2half_rn(v4 * inv));
    }

    uint4* sdst = reinterpret_cast<uint4*>(sbuf + t * 80);
#pragma unroll
    for (int q = 0; q < 5; q++) {
        uint4 v;
        v.x = (uint32_t)h[q * 8 + 0] | ((uint32_t)h[q * 8 + 1] << 16);
        v.y = (uint32_t)h[q * 8 + 2] | ((uint32_t)h[q * 8 + 3] << 16);
        v.z = (uint32_t)h[q * 8 + 4] | ((uint32_t)h[q * 8 + 5] << 16);
        v.w = (uint32_t)h[q * 8 + 6] | ((uint32_t)h[q * 8 + 7] << 16);
        sdst[q] = v;
    }
    __syncthreads();

    // Coalesced copy-out: 1280 uint4 per block
    const uint4* ssrc = reinterpret_cast<const uint4*>(sbuf);
    uint4* gdst = reinterpret_cast<uint4*>(
        reinterpret_cast<char*>(g_A) + blockX * 10);
#pragma unroll
    for (int q = 0; q < 5; q++)
        gdst[q * 256 + t] = ssrc[q * 256 + t];
}

// ---------------------------------------------------------------------------
// Producers (512 threads): pure cp.async for both A and B (same addressing,
// both row-major with 2560-byte row stride).
// ---------------------------------------------------------------------------
__device__ __forceinline__ void produce_tile(uint32_t stage_u32, int kt,
                                             const char* __restrict__ aRowBase,
                                             const char* __restrict__ bRowBase,
                                             int t) {
    const char* ag = aRowBase + kt * 128;
    const char* bg = bRowBase + kt * 128;
#pragma unroll
    for (int z = 0; z < 2; z++) {
        int c   = t + z * NTHR;           // 0..1023
        int n   = c >> 3;                 // row 0..127
        int k16 = c & 7;
        size_t gb = (size_t)n * (KDIM * 2) + k16 * 16;
        int off = n * 128 + k16 * 16;
        int sw  = off ^ ((off >> 3) & 0x70);
        cp_async16(stage_u32 + OFF_A + sw, ag + gb);
        cp_async16(stage_u32 + OFF_B + sw, bg + gb);
    }
    CP_COMMIT();
}

// ---------------------------------------------------------------------------
// Main kernel: per-CTA 128x128 GEMM over K=1280 (20 tiles of 64),
// single fp16 pass, pure cp.async double-buffered pipeline.
// 16 warps, warp tile 32M x 32N (2 m-frags x 4 n-frags), occupancy 2
// (8 warps/SMSP for LDSM latency hiding). acc = 32 regs.
// ---------------------------------------------------------------------------
__global__ void __launch_bounds__(NTHR, 2)
kan_mma_kernel(const float* __restrict__ bias, float* __restrict__ out) {
    extern __shared__ char dsm[];
    const uint32_t sb = smem_u32(dsm);
    const int t = threadIdx.x;
    const int rowBase = blockIdx.x * BM;
    const int n0      = blockIdx.y * BN;

    const char* aRowBase = reinterpret_cast<const char*>(g_A) +
                           (size_t)rowBase * (KDIM * 2);
    const char* bRowBase = reinterpret_cast<const char*>(g_Wh) +
                           (size_t)n0 * (KDIM * 2);

    // Consumer mapping: warp = (mw, nw); tile 32 rows x 32 cols
    const int w = t >> 5, lane = t & 31;
    const int mw = w >> 2;                // 0..3   (32-row group)
    const int nw = w & 3;                 // 0..3   (32-col group)

    const uint32_t a_off0 = (uint32_t)((mw * 32 + (lane & 15)) * 128 +
                                       (lane >> 4) * 16);
    const uint32_t a_m    = (a_off0 >> 3) & 0x70;
    const uint32_t b_off0 = (uint32_t)((nw * 32 + (lane & 7)) * 128 +
                                       ((lane >> 3) & 1) * 16);
    const uint32_t b_m    = (b_off0 >> 3) & 0x70;

    float acc[2][4][4];
#pragma unroll
    for (int mg = 0; mg < 2; mg++)
#pragma unroll
        for (int nb = 0; nb < 4; nb++)
#pragma unroll
            for (int j = 0; j < 4; j++) acc[mg][nb][j] = 0.0f;

    // Prologue: produce tile 0 into stage 0
    produce_tile(sb + SM_DATA, 0, aRowBase, bRowBase, t);
    CP_WAIT0();
    __syncthreads();

    for (int kt = 0; kt < NT; kt++) {
        const int b = kt & 1;
        const uint32_t cbase = sb + SM_DATA + b * STAGE;

        // ---- produce next tile into the other stage (overlaps MMA) ----
        if (kt + 1 < NT)
            produce_tile(sb + SM_DATA + (1 - b) * STAGE, kt + 1,
                         aRowBase, bRowBase, t);

        // ---- consume current tile ----
#pragma unroll
        for (int ks = 0; ks < 4; ks++) {
            const uint32_t asw = (a_off0 + ks * 32) ^ a_m;
            const uint32_t bsw = (b_off0 + ks * 32) ^ b_m;

            uint32_t a[2][4];
#pragma unroll
            for (int mg = 0; mg < 2; mg++)
                ldsm_x4(a[mg], cbase + OFF_A + asw + mg * 2048);

            uint32_t bf[4][2];
#pragma unroll
            for (int nb = 0; nb < 4; nb++)
                ldsm_x2(bf[nb], cbase + OFF_B + bsw + nb * 1024);

#pragma unroll
            for (int mg = 0; mg < 2; mg++)
#pragma unroll
                for (int nb = 0; nb < 4; nb++)
                    mma_16816(acc[mg][nb], a[mg], bf[nb]);
        }

        if (kt + 1 < NT) CP_WAIT0();
        __syncthreads();
    }

    // ---- epilogue: add bias, store ----
    {
        const int er = lane >> 2;
        const int ec = (lane & 3) * 2;
#pragma unroll
        for (int mg = 0; mg < 2; mg++) {
            const size_t row0 = (size_t)(rowBase + mw * 32 + mg * 16 + er);
#pragma unroll
            for (int nb = 0; nb < 4; nb++) {
                int c = n0 + nw * 32 + nb * 8 + ec;
                float2 b2 = *reinterpret_cast<const float2*>(bias + c);
                float2 v0, v1;
                v0.x = acc[mg][nb][0] + b2.x;
                v0.y = acc[mg][nb][1] + b2.y;
                v1.x = acc[mg][nb][2] + b2.x;
                v1.y = acc[mg][nb][3] + b2.y;
                *reinterpret_cast<float2*>(out + row0 * NOUT + c) = v0;
                *reinterpret_cast<float2*>(out + (row0 + 8) * NOUT + c) = v1;
            }
        }
    }
}

// ---------------------------------------------------------------------------
extern "C" void kernel_launch(void* const* d_in, const int* in_sizes, int n_in,
                              void* d_out, int out_size) {
    const float* x     = (const float*)d_in[0];
    const float* grid  = (const float*)d_in[1];
    const float* coef  = (const float*)d_in[2];
    const float* scale = (const float*)d_in[3];
    const float* bias  = (const float*)d_in[4];
    float* out = (float*)d_out;

    int n = in_sizes[0];
    minmax_part_kernel<<<256, 256>>>(x, n / 4);
    minmax_final_kernel<<<1, 256>>>();
    wprep_kernel<<<(NOUT * KDIM + 255) / 256, 256>>>(coef, scale);
    basis_kernel<<<BATCH * NIN / 2048, 256>>>(x, grid);

    cudaFuncSetAttribute(kan_mma_kernel,
                         cudaFuncAttributeMaxDynamicSharedMemorySize,
                         SMEM_TOTAL);
    dim3 g(BATCH / BM, NOUT / BN);
    kan_mma_kernel<<<g, NTHR, SMEM_TOTAL>>>(bias, out);
}

// round 16
// speedup vs baseline: 2.0467x; 1.0178x over previous
#include <cuda_runtime.h>
#include <cuda_fp16.h>
#include <cstdint>

#define G_EPS 1e-8f

#define BATCH 32768
#define NIN   256
#define NOUT  256
#define NG    5
#define KDIM  (NIN * NG)      // 1280

#define KT_W  64              // K columns per tile (64 fp16 = 128B SW128 row)
#define NT    (KDIM / KT_W)   // 20 K-tiles
#define BM    128             // M rows per CTA
#define BN    128             // N cols per CTA
#define NTHR  512             // 16 warps

// SMEM: two stages, each A 16KB + B 16KB
#define OFF_A  0
#define OFF_B  16384
#define STAGE  32768
#define SM_DATA 1024
#define SMEM_TOTAL (SM_DATA + 2 * STAGE)   // 66560 -> 2 CTAs/SM

__device__ float g_pmin[256];
__device__ float g_pmax[256];
__device__ float g_st[2];   // s, t for xn = s*x + t
__device__ __align__(16) __half g_Wh[NOUT * KDIM];
__device__ __align__(16) __half g_A[(size_t)BATCH * KDIM];   // 80 MB basis

// ---------------------------------------------------------------------------
// Helpers
// ---------------------------------------------------------------------------
__device__ __forceinline__ uint32_t smem_u32(const void* p) {
    uint32_t a;
    asm("{ .reg .u64 t; cvta.to.shared.u64 t, %1; cvt.u32.u64 %0, t; }"
        : "=r"(a) : "l"(p));
    return a;
}
__device__ __forceinline__ void cp_async16(uint32_t dst, const void* src) {
    asm volatile("cp.async.cg.shared.global [%0], [%1], 16;"
                 :: "r"(dst), "l"(src) : "memory");
}
#define CP_COMMIT() asm volatile("cp.async.commit_group;" ::: "memory")
#define CP_WAIT0()  asm volatile("cp.async.wait_group 0;" ::: "memory")

__device__ __forceinline__ void ldsm_x4(uint32_t* r, uint32_t addr) {
    asm volatile("ldmatrix.sync.aligned.m8n8.x4.shared.b16 {%0,%1,%2,%3}, [%4];"
                 : "=r"(r[0]), "=r"(r[1]), "=r"(r[2]), "=r"(r[3]) : "r"(addr));
}
__device__ __forceinline__ void ldsm_x2(uint32_t* r, uint32_t addr) {
    asm volatile("ldmatrix.sync.aligned.m8n8.x2.shared.b16 {%0,%1}, [%2];"
                 : "=r"(r[0]), "=r"(r[1]) : "r"(addr));
}
__device__ __forceinline__ void mma_16816(float* d, const uint32_t* a,
                                          const uint32_t* b) {
    asm volatile(
        "mma.sync.aligned.m16n8k16.row.col.f32.f16.f16.f32 "
        "{%0,%1,%2,%3}, {%4,%5,%6,%7}, {%8,%9}, {%0,%1,%2,%3};"
        : "+f"(d[0]), "+f"(d[1]), "+f"(d[2]), "+f"(d[3])
        : "r"(a[0]), "r"(a[1]), "r"(a[2]), "r"(a[3]), "r"(b[0]), "r"(b[1]));
}

// ---------------------------------------------------------------------------
// Kernel 1/2: global min/max reduction
// ---------------------------------------------------------------------------
__global__ void minmax_part_kernel(const float* __restrict__ x, int n4) {
    const float4* x4 = reinterpret_cast<const float4*>(x);
    float mn = 3.402823466e38f, mx = -3.402823466e38f;
    for (int i = blockIdx.x * blockDim.x + threadIdx.x; i < n4;
         i += gridDim.x * blockDim.x) {
        float4 v = x4[i];
        mn = fminf(mn, fminf(fminf(v.x, v.y), fminf(v.z, v.w)));
        mx = fmaxf(mx, fmaxf(fmaxf(v.x, v.y), fmaxf(v.z, v.w)));
    }
#pragma unroll
    for (int o = 16; o > 0; o >>= 1) {
        mn = fminf(mn, __shfl_xor_sync(0xffffffffu, mn, o));
        mx = fmaxf(mx, __shfl_xor_sync(0xffffffffu, mx, o));
    }
    __shared__ float smn[8], smx[8];
    int wid = threadIdx.x >> 5, lane = threadIdx.x & 31;
    if (lane == 0) { smn[wid] = mn; smx[wid] = mx; }
    __syncthreads();
    if (threadIdx.x < 8) {
        mn = smn[threadIdx.x];
        mx = smx[threadIdx.x];
#pragma unroll
        for (int o = 4; o > 0; o >>= 1) {
            mn = fminf(mn, __shfl_xor_sync(0xffu, mn, o));
            mx = fmaxf(mx, __shfl_xor_sync(0xffu, mx, o));
        }
        if (threadIdx.x == 0) { g_pmin[blockIdx.x] = mn; g_pmax[blockIdx.x] = mx; }
    }
}

__global__ void minmax_final_kernel() {
    int t = threadIdx.x;
    float mn = g_pmin[t], mx = g_pmax[t];
#pragma unroll
    for (int o = 16; o > 0; o >>= 1) {
        mn = fminf(mn, __shfl_xor_sync(0xffffffffu, mn, o));
        mx = fmaxf(mx, __shfl_xor_sync(0xffffffffu, mx, o));
    }
    __shared__ float smn[8], smx[8];
    int wid = t >> 5, lane = t & 31;
    if (lane == 0) { smn[wid] = mn; smx[wid] = mx; }
    __syncthreads();
    if (t < 8) {
        mn = smn[t];
        mx = smx[t];
#pragma unroll
        for (int o = 4; o > 0; o >>= 1) {
            mn = fminf(mn, __shfl_xor_sync(0xffu, mn, o));
            mx = fmaxf(mx, __shfl_xor_sync(0xffu, mx, o));
        }
        if (t == 0) {
            float range = mx - mn + G_EPS;
            g_st[0] = 2.0f / range;
            g_st[1] = -2.0f * mn / range - 1.0f;
        }
    }
}

// ---------------------------------------------------------------------------
// Kernel 3: W = coef*scale -> fp16
// ---------------------------------------------------------------------------
__global__ void wprep_kernel(const float* __restrict__ coef,
                             const float* __restrict__ scale) {
    int idx = blockIdx.x * blockDim.x + threadIdx.x;
    if (idx < NOUT * KDIM) {
        int o   = idx / KDIM;
        int rem = idx - o * KDIM;
        int i   = rem / NG;
        float w = coef[idx] * scale[o * NIN + i];
        g_Wh[idx] = __float2half_rn(w);
    }
}

// ---------------------------------------------------------------------------
// Kernel 4: basis matrix A[b][i*5+g] (fp16), 8 x-values per thread.
// Compute into smem, then fully-coalesced uint4 copy-out.
// ---------------------------------------------------------------------------
__global__ void __launch_bounds__(256)
basis_kernel(const float* __restrict__ x, const float* __restrict__ grid) {
    __shared__ char sbuf[256 * 80];     // 20 KB staging
    const int t = threadIdx.x;
    const size_t blockX = (size_t)blockIdx.x * 2048;     // 256 thr * 8 x
    const size_t ii = blockX + (size_t)t * 8;

    const float s  = g_st[0];
    const float tt = g_st[1];
    const float g0 = __ldg(grid + 0), g1 = __ldg(grid + 1),
                g2 = __ldg(grid + 2), g3 = __ldg(grid + 3),
                g4 = __ldg(grid + 4);

    float4 xa = *reinterpret_cast<const float4*>(x + ii);
    float4 xb = *reinterpret_cast<const float4*>(x + ii + 4);
    float xe[8] = {xa.x, xa.y, xa.z, xa.w, xb.x, xb.y, xb.z, xb.w};

    unsigned short h[40];
#pragma unroll
    for (int e = 0; e < 8; e++) {
        float xn = fmaf(xe[e], s, tt);
        float d, v0, v1, v2, v3, v4;
        d = fabsf(xn - g0); v0 = fmaxf(fmaf(-d * d, d, 1.0f), 0.0f);
        d = fabsf(xn - g1); v1 = fmaxf(fmaf(-d * d, d, 1.0f), 0.0f);
        d = fabsf(xn - g2); v2 = fmaxf(fmaf(-d * d, d, 1.0f), 0.0f);
        d = fabsf(xn - g3); v3 = fmaxf(fmaf(-d * d, d, 1.0f), 0.0f);
        d = fabsf(xn - g4); v4 = fmaxf(fmaf(-d * d, d, 1.0f), 0.0f);
        float inv = __fdividef(1.0f, v0 + v1 + v2 + v3 + v4 + G_EPS);
        h[e * 5 + 0] = __half_as_ushort(__float2half_rn(v0 * inv));
        h[e * 5 + 1] = __half_as_ushort(__float2half_rn(v1 * inv));
        h[e * 5 + 2] = __half_as_ushort(__float2half_rn(v2 * inv));
        h[e * 5 + 3] = __half_as_ushort(__float2half_rn(v3 * inv));
        h[e * 5 + 4] = __half_as_ushort(__float2half_rn(v4 * inv));
    }

    uint4* sdst = reinterpret_cast<uint4*>(sbuf + t * 80);
#pragma unroll
    for (int q = 0; q < 5; q++) {
        uint4 v;
        v.x = (uint32_t)h[q * 8 + 0] | ((uint32_t)h[q * 8 + 1] << 16);
        v.y = (uint32_t)h[q * 8 + 2] | ((uint32_t)h[q * 8 + 3] << 16);
        v.z = (uint32_t)h[q * 8 + 4] | ((uint32_t)h[q * 8 + 5] << 16);
        v.w = (uint32_t)h[q * 8 + 6] | ((uint32_t)h[q * 8 + 7] << 16);
        sdst[q] = v;
    }
    __syncthreads();

    // Coalesced copy-out: 1280 uint4 per block
    const uint4* ssrc = reinterpret_cast<const uint4*>(sbuf);
    uint4* gdst = reinterpret_cast<uint4*>(
        reinterpret_cast<char*>(g_A) + blockX * 10);
#pragma unroll
    for (int q = 0; q < 5; q++)
        gdst[q * 256 + t] = ssrc[q * 256 + t];
}

// ---------------------------------------------------------------------------
// Producers (512 threads): pure cp.async for both A and B (same addressing,
// both row-major with 2560-byte row stride).
// ---------------------------------------------------------------------------
__device__ __forceinline__ void produce_tile(uint32_t stage_u32, int kt,
                                             const char* __restrict__ aRowBase,
                                             const char* __restrict__ bRowBase,
                                             int t) {
    const char* ag = aRowBase + kt * 128;
    const char* bg = bRowBase + kt * 128;
#pragma unroll
    for (int z = 0; z < 2; z++) {
        int c   = t + z * NTHR;           // 0..1023
        int n   = c >> 3;                 // row 0..127
        int k16 = c & 7;
        size_t gb = (size_t)n * (KDIM * 2) + k16 * 16;
        int off = n * 128 + k16 * 16;
        int sw  = off ^ ((off >> 3) & 0x70);
        cp_async16(stage_u32 + OFF_A + sw, ag + gb);
        cp_async16(stage_u32 + OFF_B + sw, bg + gb);
    }
    CP_COMMIT();
}

// ---------------------------------------------------------------------------
// Main kernel: per-CTA 128x128 GEMM over K=1280 (20 tiles of 64),
// single fp16 pass, pure cp.async double-buffered pipeline.
// 16 warps, warp tile 32M x 32N, occupancy 2.
// Grid is (N-blocks, M-blocks) so the two CTAs sharing an A row-block have
// ADJACENT linear bids -> co-resident -> second A read hits L2.
// ---------------------------------------------------------------------------
__global__ void __launch_bounds__(NTHR, 2)
kan_mma_kernel(const float* __restrict__ bias, float* __restrict__ out) {
    extern __shared__ char dsm[];
    const uint32_t sb = smem_u32(dsm);
    const int t = threadIdx.x;
    const int rowBase = blockIdx.y * BM;      // M block (slow grid dim)
    const int n0      = blockIdx.x * BN;      // N block (fast grid dim)

    const char* aRowBase = reinterpret_cast<const char*>(g_A) +
                           (size_t)rowBase * (KDIM * 2);
    const char* bRowBase = reinterpret_cast<const char*>(g_Wh) +
                           (size_t)n0 * (KDIM * 2);

    // Consumer mapping: warp = (mw, nw); tile 32 rows x 32 cols
    const int w = t >> 5, lane = t & 31;
    const int mw = w >> 2;                // 0..3   (32-row group)
    const int nw = w & 3;                 // 0..3   (32-col group)

    const uint32_t a_off0 = (uint32_t)((mw * 32 + (lane & 15)) * 128 +
                                       (lane >> 4) * 16);
    const uint32_t a_m    = (a_off0 >> 3) & 0x70;
    const uint32_t b_off0 = (uint32_t)((nw * 32 + (lane & 7)) * 128 +
                                       ((lane >> 3) & 1) * 16);
    const uint32_t b_m    = (b_off0 >> 3) & 0x70;

    float acc[2][4][4];
#pragma unroll
    for (int mg = 0; mg < 2; mg++)
#pragma unroll
        for (int nb = 0; nb < 4; nb++)
#pragma unroll
            for (int j = 0; j < 4; j++) acc[mg][nb][j] = 0.0f;

    // Prologue: produce tile 0 into stage 0
    produce_tile(sb + SM_DATA, 0, aRowBase, bRowBase, t);
    CP_WAIT0();
    __syncthreads();

    for (int kt = 0; kt < NT; kt++) {
        const int b = kt & 1;
        const uint32_t cbase = sb + SM_DATA + b * STAGE;

        // ---- produce next tile into the other stage (overlaps MMA) ----
        if (kt + 1 < NT)
            produce_tile(sb + SM_DATA + (1 - b) * STAGE, kt + 1,
                         aRowBase, bRowBase, t);

        // ---- consume current tile ----
#pragma unroll
        for (int ks = 0; ks < 4; ks++) {
            const uint32_t asw = (a_off0 + ks * 32) ^ a_m;
            const uint32_t bsw = (b_off0 + ks * 32) ^ b_m;

            uint32_t a[2][4];
#pragma unroll
            for (int mg = 0; mg < 2; mg++)
                ldsm_x4(a[mg], cbase + OFF_A + asw + mg * 2048);

            uint32_t bf[4][2];
#pragma unroll
            for (int nb = 0; nb < 4; nb++)
                ldsm_x2(bf[nb], cbase + OFF_B + bsw + nb * 1024);

#pragma unroll
            for (int mg = 0; mg < 2; mg++)
#pragma unroll
                for (int nb = 0; nb < 4; nb++)
                    mma_16816(acc[mg][nb], a[mg], bf[nb]);
        }

        if (kt + 1 < NT) CP_WAIT0();
        __syncthreads();
    }

    // ---- epilogue: add bias, store ----
    {
        const int er = lane >> 2;
        const int ec = (lane & 3) * 2;
#pragma unroll
        for (int mg = 0; mg < 2; mg++) {
            const size_t row0 = (size_t)(rowBase + mw * 32 + mg * 16 + er);
#pragma unroll
            for (int nb = 0; nb < 4; nb++) {
                int c = n0 + nw * 32 + nb * 8 + ec;
                float2 b2 = *reinterpret_cast<const float2*>(bias + c);
                float2 v0, v1;
                v0.x = acc[mg][nb][0] + b2.x;
                v0.y = acc[mg][nb][1] + b2.y;
                v1.x = acc[mg][nb][2] + b2.x;
                v1.y = acc[mg][nb][3] + b2.y;
                *reinterpret_cast<float2*>(out + row0 * NOUT + c) = v0;
                *reinterpret_cast<float2*>(out + (row0 + 8) * NOUT + c) = v1;
            }
        }
    }
}

// ---------------------------------------------------------------------------
extern "C" void kernel_launch(void* const* d_in, const int* in_sizes, int n_in,
                              void* d_out, int out_size) {
    const float* x     = (const float*)d_in[0];
    const float* grid  = (const float*)d_in[1];
    const float* coef  = (const float*)d_in[2];
    const float* scale = (const float*)d_in[3];
    const float* bias  = (const float*)d_in[4];
    float* out = (float*)d_out;

    int n = in_sizes[0];
    minmax_part_kernel<<<256, 256>>>(x, n / 4);
    minmax_final_kernel<<<1, 256>>>();
    wprep_kernel<<<(NOUT * KDIM + 255) / 256, 256>>>(coef, scale);
    basis_kernel<<<BATCH * NIN / 2048, 256>>>(x, grid);

    cudaFuncSetAttribute(kan_mma_kernel,
                         cudaFuncAttributeMaxDynamicSharedMemorySize,
                         SMEM_TOTAL);
    dim3 g(NOUT / BN, BATCH / BM);   // N fast, M slow -> A L2 reuse
    kan_mma_kernel<<<g, NTHR, SMEM_TOTAL>>>(bias, out);
}